// round 1
// baseline (speedup 1.0000x reference)
#include <cuda_runtime.h>
#include <math.h>

#define B_ 2
#define T_ 4096
#define H_ 12
#define D_ 64
#define C_ 768
#define BT_ (B_*T_)

// Scratch (static device globals — allocation-free per harness rules)
__device__ float g_q[(size_t)B_*H_*T_*D_];
__device__ float g_k[(size_t)B_*H_*T_*D_];
__device__ float g_v[(size_t)B_*H_*T_*D_];
__device__ float g_ctx[(size_t)BT_*C_];

// ---------------------------------------------------------------------------
// SGEMM: out = A (M x K, row-major) @ W^T, W is (N x K, row-major).
// M=8192, N=K=768. 128x128 tile, BK=8, 256 threads, 8x8 per-thread.
// MODE 0: scatter output into (B,H,T,D) head layout. MODE 1: plain row-major.
// ---------------------------------------------------------------------------
template<int MODE>
__global__ __launch_bounds__(256) void sgemm_nt(const float* __restrict__ A,
                                                const float* __restrict__ W,
                                                float* __restrict__ out)
{
    const int K = C_;
    __shared__ float As[8][128];
    __shared__ float Bs[8][128];

    const int tid  = threadIdx.x;
    const int m0   = blockIdx.y * 128;
    const int n0   = blockIdx.x * 128;
    const int lrow = tid >> 1;          // 0..127
    const int lcol = (tid & 1) * 4;     // 0 or 4
    const int tr   = tid >> 4;          // 0..15
    const int tc   = tid & 15;          // 0..15

    float acc[8][8];
    #pragma unroll
    for (int i = 0; i < 8; i++)
        #pragma unroll
        for (int j = 0; j < 8; j++) acc[i][j] = 0.f;

    for (int kk = 0; kk < K; kk += 8) {
        float4 av = *(const float4*)(A + (size_t)(m0 + lrow) * K + kk + lcol);
        float4 wv = *(const float4*)(W + (size_t)(n0 + lrow) * K + kk + lcol);
        As[lcol + 0][lrow] = av.x; As[lcol + 1][lrow] = av.y;
        As[lcol + 2][lrow] = av.z; As[lcol + 3][lrow] = av.w;
        Bs[lcol + 0][lrow] = wv.x; Bs[lcol + 1][lrow] = wv.y;
        Bs[lcol + 2][lrow] = wv.z; Bs[lcol + 3][lrow] = wv.w;
        __syncthreads();

        #pragma unroll
        for (int k = 0; k < 8; k++) {
            float rm[8], rn[8];
            #pragma unroll
            for (int i = 0; i < 8; i++) rm[i] = As[k][tr * 8 + i];
            #pragma unroll
            for (int j = 0; j < 8; j++) rn[j] = Bs[k][tc * 8 + j];
            #pragma unroll
            for (int i = 0; i < 8; i++)
                #pragma unroll
                for (int j = 0; j < 8; j++) acc[i][j] += rm[i] * rn[j];
        }
        __syncthreads();
    }

    #pragma unroll
    for (int i = 0; i < 8; i++) {
        const int m = m0 + tr * 8 + i;
        const int b = m >> 12;          // T_ = 4096
        const int t = m & 4095;
        #pragma unroll
        for (int j = 0; j < 8; j++) {
            const int n = n0 + tc * 8 + j;
            if (MODE == 0) {
                const int h = n >> 6, d = n & 63;
                out[(((size_t)(b * H_ + h)) * T_ + t) * D_ + d] = acc[i][j];
            } else {
                out[(size_t)m * C_ + n] = acc[i][j];
            }
        }
    }
}

// ---------------------------------------------------------------------------
// Causal flash attention. Q/K/V in (B*H, T, D) layout.
// Grid: (T/64, B*H). 256 threads: r = tid/4 (query row in tile), c = tid&3.
// Thread owns S/P cols j = jj*4+c and O cols d = i*4+c (interleaved ->
// conflict-free LDS). P broadcast over the 4-lane row group via shfl.
// smem: Qs[64][68] + Ks[64][68] + Vs[64][64] = 51200 B (dynamic).
// ---------------------------------------------------------------------------
#define ATTN_SMEM ((2*64*68 + 64*64) * 4)

__global__ __launch_bounds__(256) void attn_fwd(const float* __restrict__ Q,
                                                const float* __restrict__ K,
                                                const float* __restrict__ V,
                                                float* __restrict__ ctx)
{
    extern __shared__ float sm[];
    float* Qs = sm;               // [64][68]
    float* Ks = sm + 64 * 68;     // [64][68]
    float* Vs = sm + 2 * 64 * 68; // [64][64]

    const int tid  = threadIdx.x;
    const int lane = tid & 31;
    const int r    = tid >> 2;    // 0..63
    const int c    = tid & 3;     // 0..3
    const int qt   = blockIdx.x;
    const int bh   = blockIdx.y;
    const size_t base_bh = (size_t)bh * T_ * D_;
    const int qglob = qt * 64 + r;

    // Load Q tile (64x64) into padded smem
    {
        const float* src = Q + base_bh + (size_t)qt * 64 * D_;
        #pragma unroll
        for (int it = 0; it < 4; it++) {
            int lin = tid + it * 256;        // float4 index 0..1023
            int row = lin >> 4;
            int col = (lin & 15) << 2;
            *(float4*)(Qs + row * 68 + col) = *(const float4*)(src + row * 64 + col);
        }
    }

    float O[16];
    #pragma unroll
    for (int i = 0; i < 16; i++) O[i] = 0.f;
    float m_run = -1e30f, l_run = 0.f;

    for (int kt = 0; kt <= qt; kt++) {
        __syncthreads();   // previous-iteration smem reads done
        {
            const float* ksrc = K + base_bh + (size_t)kt * 64 * D_;
            const float* vsrc = V + base_bh + (size_t)kt * 64 * D_;
            #pragma unroll
            for (int it = 0; it < 4; it++) {
                int lin = tid + it * 256;
                int row = lin >> 4;
                int col = (lin & 15) << 2;
                *(float4*)(Ks + row * 68 + col) = *(const float4*)(ksrc + row * 64 + col);
                *(float4*)(Vs + lin * 4)        = *(const float4*)(vsrc + lin * 4);
            }
        }
        __syncthreads();

        // S[jj] = Q[r,:] . K[jj*4+c,:]
        float S[16];
        #pragma unroll
        for (int jj = 0; jj < 16; jj++) S[jj] = 0.f;
        #pragma unroll
        for (int k0 = 0; k0 < 64; k0 += 4) {
            float4 qv = *(const float4*)(Qs + r * 68 + k0);
            #pragma unroll
            for (int jj = 0; jj < 16; jj++) {
                float4 kv = *(const float4*)(Ks + (jj * 4 + c) * 68 + k0);
                S[jj] += qv.x * kv.x + qv.y * kv.y + qv.z * kv.z + qv.w * kv.w;
            }
        }
        const float scale = 0.125f;   // 1/sqrt(64)
        if (kt == qt) {
            #pragma unroll
            for (int jj = 0; jj < 16; jj++) {
                int key = kt * 64 + jj * 4 + c;
                S[jj] = (key <= qglob) ? S[jj] * scale : -1e30f;
            }
        } else {
            #pragma unroll
            for (int jj = 0; jj < 16; jj++) S[jj] *= scale;
        }

        // row max over 16 local + 4-lane group
        float mx = S[0];
        #pragma unroll
        for (int jj = 1; jj < 16; jj++) mx = fmaxf(mx, S[jj]);
        mx = fmaxf(mx, __shfl_xor_sync(0xffffffffu, mx, 1));
        mx = fmaxf(mx, __shfl_xor_sync(0xffffffffu, mx, 2));

        const float m_new = fmaxf(m_run, mx);
        const float corr  = __expf(m_run - m_new);
        float P[16];
        float ps = 0.f;
        #pragma unroll
        for (int jj = 0; jj < 16; jj++) { P[jj] = __expf(S[jj] - m_new); ps += P[jj]; }
        ps += __shfl_xor_sync(0xffffffffu, ps, 1);
        ps += __shfl_xor_sync(0xffffffffu, ps, 2);
        l_run = l_run * corr + ps;
        m_run = m_new;
        #pragma unroll
        for (int i = 0; i < 16; i++) O[i] *= corr;

        // O[r, i*4+c] += sum_j P[r,j] * V[j, i*4+c]
        #pragma unroll
        for (int g = 0; g < 4; g++) {
            const int srcLane = (lane & ~3) | g;
            #pragma unroll
            for (int jj = 0; jj < 16; jj++) {
                const float p = __shfl_sync(0xffffffffu, P[jj], srcLane);
                const float* vrow = Vs + (jj * 4 + g) * 64;
                #pragma unroll
                for (int i = 0; i < 16; i++) O[i] += p * vrow[i * 4 + c];
            }
        }
    }

    const float inv = 1.f / l_run;
    const int b = bh / H_, h = bh % H_;
    const size_t obase = ((size_t)b * T_ + qglob) * C_ + h * 64 + c;
    #pragma unroll
    for (int i = 0; i < 16; i++) ctx[obase + i * 4] = O[i] * inv;
}

// ---------------------------------------------------------------------------
extern "C" void kernel_launch(void* const* d_in, const int* in_sizes, int n_in,
                              void* d_out, int out_size)
{
    (void)in_sizes; (void)n_in; (void)out_size;
    const float* x  = (const float*)d_in[0];
    const float* wq = (const float*)d_in[1];
    const float* wk = (const float*)d_in[2];
    const float* wv = (const float*)d_in[3];
    const float* wo = (const float*)d_in[4];
    float* out = (float*)d_out;

    float *q, *k, *v, *ctx;
    cudaGetSymbolAddress((void**)&q,   g_q);
    cudaGetSymbolAddress((void**)&k,   g_k);
    cudaGetSymbolAddress((void**)&v,   g_v);
    cudaGetSymbolAddress((void**)&ctx, g_ctx);

    const dim3 ggrid(C_ / 128, BT_ / 128);
    sgemm_nt<0><<<ggrid, 256>>>(x, wq, q);
    sgemm_nt<0><<<ggrid, 256>>>(x, wk, k);
    sgemm_nt<0><<<ggrid, 256>>>(x, wv, v);

    cudaFuncSetAttribute(attn_fwd, cudaFuncAttributeMaxDynamicSharedMemorySize, ATTN_SMEM);
    attn_fwd<<<dim3(T_ / 64, B_ * H_), 256, ATTN_SMEM>>>(q, k, v, ctx);

    sgemm_nt<1><<<ggrid, 256>>>(ctx, wo, out);
}

// round 2
// speedup vs baseline: 1.6173x; 1.6173x over previous
#include <cuda_runtime.h>
#include <math.h>

#define B_ 2
#define T_ 4096
#define H_ 12
#define D_ 64
#define C_ 768
#define BT_ (B_*T_)

// Scratch (static device globals — allocation-free per harness rules)
__device__ float g_q[(size_t)B_*H_*T_*D_];
__device__ float g_k[(size_t)B_*H_*T_*D_];
__device__ float g_v[(size_t)B_*H_*T_*D_];
__device__ float g_ctx[(size_t)BT_*C_];

// ---------------------------------------------------------------------------
// SGEMM: out = A (M x K, row-major) @ W^T, W is (N x K, row-major).
// M=8192, N=K=768. 128x128 tile, BK=8, 256 threads, 8x8 per-thread.
// MODE 0: scatter output into (B,H,T,D) head layout. MODE 1: plain row-major.
// ---------------------------------------------------------------------------
template<int MODE>
__global__ __launch_bounds__(256) void sgemm_nt(const float* __restrict__ A,
                                                const float* __restrict__ W,
                                                float* __restrict__ out)
{
    const int K = C_;
    __shared__ float As[8][128];
    __shared__ float Bs[8][128];

    const int tid  = threadIdx.x;
    const int m0   = blockIdx.y * 128;
    const int n0   = blockIdx.x * 128;
    const int lrow = tid >> 1;          // 0..127
    const int lcol = (tid & 1) * 4;     // 0 or 4
    const int tr   = tid >> 4;          // 0..15
    const int tc   = tid & 15;          // 0..15

    float acc[8][8];
    #pragma unroll
    for (int i = 0; i < 8; i++)
        #pragma unroll
        for (int j = 0; j < 8; j++) acc[i][j] = 0.f;

    for (int kk = 0; kk < K; kk += 8) {
        float4 av = *(const float4*)(A + (size_t)(m0 + lrow) * K + kk + lcol);
        float4 wv = *(const float4*)(W + (size_t)(n0 + lrow) * K + kk + lcol);
        As[lcol + 0][lrow] = av.x; As[lcol + 1][lrow] = av.y;
        As[lcol + 2][lrow] = av.z; As[lcol + 3][lrow] = av.w;
        Bs[lcol + 0][lrow] = wv.x; Bs[lcol + 1][lrow] = wv.y;
        Bs[lcol + 2][lrow] = wv.z; Bs[lcol + 3][lrow] = wv.w;
        __syncthreads();

        #pragma unroll
        for (int k = 0; k < 8; k++) {
            float rm[8], rn[8];
            #pragma unroll
            for (int i = 0; i < 8; i++) rm[i] = As[k][tr * 8 + i];
            #pragma unroll
            for (int j = 0; j < 8; j++) rn[j] = Bs[k][tc * 8 + j];
            #pragma unroll
            for (int i = 0; i < 8; i++)
                #pragma unroll
                for (int j = 0; j < 8; j++) acc[i][j] += rm[i] * rn[j];
        }
        __syncthreads();
    }

    #pragma unroll
    for (int i = 0; i < 8; i++) {
        const int m = m0 + tr * 8 + i;
        const int b = m >> 12;          // T_ = 4096
        const int t = m & 4095;
        #pragma unroll
        for (int j = 0; j < 8; j++) {
            const int n = n0 + tc * 8 + j;
            if (MODE == 0) {
                const int h = n >> 6, d = n & 63;
                out[(((size_t)(b * H_ + h)) * T_ + t) * D_ + d] = acc[i][j];
            } else {
                out[(size_t)m * C_ + n] = acc[i][j];
            }
        }
    }
}

// ---------------------------------------------------------------------------
// Causal flash attention, register-blocked GEMM style.
// Q/K/V in (B*H, T, D) layout. Grid: (T/64, B*H). 256 threads.
// Thread grid 16x16: tr=tid>>4 owns S/O rows tr*4..+3, tc=tid&15 owns cols
// tc*4..+3. All smem operands stored inner-dim-major so compute loads are
// LDS.128 with rm broadcast:
//   Qt[d][r], Kt[d][j]  (transposed on load, stride 68)
//   Vs[j][d], Ps[j][r]  (stride 68)
// Softmax reduces across the 16-lane tc group via shfl_xor.
// ---------------------------------------------------------------------------
#define AS 68
#define ATTN_SMEM (4 * 64 * AS * 4)

__global__ __launch_bounds__(256, 2) void attn_fwd(const float* __restrict__ Q,
                                                   const float* __restrict__ K,
                                                   const float* __restrict__ V,
                                                   float* __restrict__ ctx)
{
    extern __shared__ float sm[];
    float* Qt = sm;                // [64][AS]  Qt[d][r]
    float* Kt = sm + 64 * AS;      // [64][AS]  Kt[d][j]
    float* Vs = sm + 2 * 64 * AS;  // [64][AS]  Vs[j][d]
    float* Ps = sm + 3 * 64 * AS;  // [64][AS]  Ps[j][r]

    const int tid = threadIdx.x;
    const int tr  = tid >> 4;      // 0..15 : rows tr*4..+3
    const int tc  = tid & 15;      // 0..15 : cols tc*4..+3
    const int qt  = blockIdx.x;
    const int bh  = blockIdx.y;
    const size_t base_bh = (size_t)bh * T_ * D_;

    // Load Q tile transposed: Qt[d][r]
    {
        const float* src = Q + base_bh + (size_t)qt * 64 * D_;
        #pragma unroll
        for (int it = 0; it < 4; it++) {
            int lin = tid + it * 256;          // float4 index 0..1023
            int r   = lin >> 4;
            int c4  = (lin & 15) << 2;
            float4 qv = *(const float4*)(src + r * 64 + c4);
            Qt[(c4 + 0) * AS + r] = qv.x;
            Qt[(c4 + 1) * AS + r] = qv.y;
            Qt[(c4 + 2) * AS + r] = qv.z;
            Qt[(c4 + 3) * AS + r] = qv.w;
        }
    }

    float O[4][4];
    #pragma unroll
    for (int i = 0; i < 4; i++)
        #pragma unroll
        for (int j = 0; j < 4; j++) O[i][j] = 0.f;
    float m_i[4], l_i[4];
    #pragma unroll
    for (int i = 0; i < 4; i++) { m_i[i] = -1e30f; l_i[i] = 0.f; }

    for (int kt = 0; kt <= qt; kt++) {
        __syncthreads();   // prior-iter smem readers done
        {
            const float* ksrc = K + base_bh + (size_t)kt * 64 * D_;
            const float* vsrc = V + base_bh + (size_t)kt * 64 * D_;
            #pragma unroll
            for (int it = 0; it < 4; it++) {
                int lin = tid + it * 256;
                int r   = lin >> 4;
                int c4  = (lin & 15) << 2;
                float4 kv = *(const float4*)(ksrc + r * 64 + c4);
                Kt[(c4 + 0) * AS + r] = kv.x;
                Kt[(c4 + 1) * AS + r] = kv.y;
                Kt[(c4 + 2) * AS + r] = kv.z;
                Kt[(c4 + 3) * AS + r] = kv.w;
                *(float4*)(Vs + r * AS + c4) = *(const float4*)(vsrc + r * 64 + c4);
            }
        }
        __syncthreads();

        // S[4][4] = Q[tr*4..][:] . K[tc*4..][:]^T
        float S[4][4];
        #pragma unroll
        for (int i = 0; i < 4; i++)
            #pragma unroll
            for (int j = 0; j < 4; j++) S[i][j] = 0.f;

        #pragma unroll 8
        for (int d = 0; d < 64; d++) {
            float4 a = *(const float4*)(Qt + d * AS + tr * 4);
            float4 b = *(const float4*)(Kt + d * AS + tc * 4);
            S[0][0] += a.x * b.x; S[0][1] += a.x * b.y; S[0][2] += a.x * b.z; S[0][3] += a.x * b.w;
            S[1][0] += a.y * b.x; S[1][1] += a.y * b.y; S[1][2] += a.y * b.z; S[1][3] += a.y * b.w;
            S[2][0] += a.z * b.x; S[2][1] += a.z * b.y; S[2][2] += a.z * b.z; S[2][3] += a.z * b.w;
            S[3][0] += a.w * b.x; S[3][1] += a.w * b.y; S[3][2] += a.w * b.z; S[3][3] += a.w * b.w;
        }

        const float scale = 0.125f;   // 1/sqrt(64)
        if (kt == qt) {
            #pragma unroll
            for (int i = 0; i < 4; i++)
                #pragma unroll
                for (int j = 0; j < 4; j++)
                    S[i][j] = (tc * 4 + j <= tr * 4 + i) ? S[i][j] * scale : -1e30f;
        } else {
            #pragma unroll
            for (int i = 0; i < 4; i++)
                #pragma unroll
                for (int j = 0; j < 4; j++) S[i][j] *= scale;
        }

        // Row-wise online softmax (reduce across the 16-lane tc group)
        float P[4][4];
        #pragma unroll
        for (int i = 0; i < 4; i++) {
            float mx = fmaxf(fmaxf(S[i][0], S[i][1]), fmaxf(S[i][2], S[i][3]));
            mx = fmaxf(mx, __shfl_xor_sync(0xffffffffu, mx, 1));
            mx = fmaxf(mx, __shfl_xor_sync(0xffffffffu, mx, 2));
            mx = fmaxf(mx, __shfl_xor_sync(0xffffffffu, mx, 4));
            mx = fmaxf(mx, __shfl_xor_sync(0xffffffffu, mx, 8));
            const float m_new = fmaxf(m_i[i], mx);
            const float corr  = __expf(m_i[i] - m_new);
            float ps = 0.f;
            #pragma unroll
            for (int j = 0; j < 4; j++) { P[i][j] = __expf(S[i][j] - m_new); ps += P[i][j]; }
            ps += __shfl_xor_sync(0xffffffffu, ps, 1);
            ps += __shfl_xor_sync(0xffffffffu, ps, 2);
            ps += __shfl_xor_sync(0xffffffffu, ps, 4);
            ps += __shfl_xor_sync(0xffffffffu, ps, 8);
            l_i[i] = l_i[i] * corr + ps;
            m_i[i] = m_new;
            #pragma unroll
            for (int j = 0; j < 4; j++) O[i][j] *= corr;
        }

        // Store P transposed: Ps[j][r] (float4 along r)
        #pragma unroll
        for (int jc = 0; jc < 4; jc++) {
            *(float4*)(Ps + (tc * 4 + jc) * AS + tr * 4) =
                make_float4(P[0][jc], P[1][jc], P[2][jc], P[3][jc]);
        }
        __syncthreads();

        // O[4][4] += P(64-wide) @ V
        #pragma unroll 8
        for (int j = 0; j < 64; j++) {
            float4 p = *(const float4*)(Ps + j * AS + tr * 4);
            float4 v = *(const float4*)(Vs + j * AS + tc * 4);
            O[0][0] += p.x * v.x; O[0][1] += p.x * v.y; O[0][2] += p.x * v.z; O[0][3] += p.x * v.w;
            O[1][0] += p.y * v.x; O[1][1] += p.y * v.y; O[1][2] += p.y * v.z; O[1][3] += p.y * v.w;
            O[2][0] += p.z * v.x; O[2][1] += p.z * v.y; O[2][2] += p.z * v.z; O[2][3] += p.z * v.w;
            O[3][0] += p.w * v.x; O[3][1] += p.w * v.y; O[3][2] += p.w * v.z; O[3][3] += p.w * v.w;
        }
    }

    // Epilogue: normalize and write to (B, T, C) layout
    const int b = bh / H_, h = bh % H_;
    #pragma unroll
    for (int i = 0; i < 4; i++) {
        const float inv = 1.f / l_i[i];
        const int trow = qt * 64 + tr * 4 + i;
        float4 o = make_float4(O[i][0] * inv, O[i][1] * inv, O[i][2] * inv, O[i][3] * inv);
        *(float4*)(ctx + ((size_t)b * T_ + trow) * C_ + h * 64 + tc * 4) = o;
    }
}

// ---------------------------------------------------------------------------
extern "C" void kernel_launch(void* const* d_in, const int* in_sizes, int n_in,
                              void* d_out, int out_size)
{
    (void)in_sizes; (void)n_in; (void)out_size;
    const float* x  = (const float*)d_in[0];
    const float* wq = (const float*)d_in[1];
    const float* wk = (const float*)d_in[2];
    const float* wv = (const float*)d_in[3];
    const float* wo = (const float*)d_in[4];
    float* out = (float*)d_out;

    float *q, *k, *v, *ctx;
    cudaGetSymbolAddress((void**)&q,   g_q);
    cudaGetSymbolAddress((void**)&k,   g_k);
    cudaGetSymbolAddress((void**)&v,   g_v);
    cudaGetSymbolAddress((void**)&ctx, g_ctx);

    const dim3 ggrid(C_ / 128, BT_ / 128);
    sgemm_nt<0><<<ggrid, 256>>>(x, wq, q);
    sgemm_nt<0><<<ggrid, 256>>>(x, wk, k);
    sgemm_nt<0><<<ggrid, 256>>>(x, wv, v);

    cudaFuncSetAttribute(attn_fwd, cudaFuncAttributeMaxDynamicSharedMemorySize, ATTN_SMEM);
    attn_fwd<<<dim3(T_ / 64, B_ * H_), 256, ATTN_SMEM>>>(q, k, v, ctx);

    sgemm_nt<1><<<ggrid, 256>>>(ctx, wo, out);
}

// round 7
// speedup vs baseline: 1.9050x; 1.1778x over previous
#include <cuda_runtime.h>
#include <cuda_bf16.h>
#include <cstdint>
#include <math.h>

#define B_ 2
#define T_ 4096
#define H_ 12
#define D_ 64
#define C_ 768
#define BT_ (B_*T_)
#define K2 2304   // 3 * C_ : [hi | lo | hi] x [hi | hi | lo]

// Scratch (static device globals — allocation-free per harness rules)
__device__ float g_q[(size_t)B_*H_*T_*D_];
__device__ float g_k[(size_t)B_*H_*T_*D_];
__device__ float g_v[(size_t)B_*H_*T_*D_];
__device__ float g_ctx[(size_t)BT_*C_];
__device__ __nv_bfloat16 g_x2[(size_t)BT_*K2];
__device__ __nv_bfloat16 g_ctx2[(size_t)BT_*K2];
__device__ __nv_bfloat16 g_wq2[(size_t)C_*K2];
__device__ __nv_bfloat16 g_wk2[(size_t)C_*K2];
__device__ __nv_bfloat16 g_wv2[(size_t)C_*K2];
__device__ __nv_bfloat16 g_wo2[(size_t)C_*K2];

// ---------------------------------------------------------------------------
// fp32 -> compensated bf16 split, K-concatenated.
// ISW=0 (activations): [hi | lo | hi]   ISW=1 (weights): [hi | hi | lo]
// ---------------------------------------------------------------------------
template<int ISW>
__global__ __launch_bounds__(256) void conv_hilo(const float* __restrict__ in,
                                                 __nv_bfloat16* __restrict__ out,
                                                 int nelem)
{
    int idx = blockIdx.x * 256 + threadIdx.x;
    if (idx >= nelem) return;
    int r = idx / C_, c = idx % C_;
    float x = in[idx];
    __nv_bfloat16 hi = __float2bfloat16(x);
    __nv_bfloat16 lo = __float2bfloat16(x - __bfloat162float(hi));
    __nv_bfloat16* o = out + (size_t)r * K2;
    if (ISW) { o[c] = hi; o[c + C_] = hi; o[c + 2*C_] = lo; }
    else     { o[c] = hi; o[c + C_] = lo; o[c + 2*C_] = hi; }
}

// ---------------------------------------------------------------------------
// bf16 HMMA NT GEMM: out(M x 768) = A2(M x K2) @ B2(768 x K2)^T, fp32 accum.
// CTA 128x128, 8 warps in 4(m) x 2(n), warp tile 32x64, mma m16n8k16.
// MODE 0: scatter to (B,H,T,D). MODE 1: row-major (M, 768).
// smem rows padded to 40 halves (80 B) -> conflict-free quad-pattern LDS.32.
// ---------------------------------------------------------------------------
#define SAS 40

__device__ __forceinline__ void mma_bf16(float c[4], const uint32_t a[4], const uint32_t b[2])
{
    asm volatile(
        "mma.sync.aligned.m16n8k16.row.col.f32.bf16.bf16.f32 "
        "{%0,%1,%2,%3}, {%4,%5,%6,%7}, {%8,%9}, {%0,%1,%2,%3};"
        : "+f"(c[0]), "+f"(c[1]), "+f"(c[2]), "+f"(c[3])
        : "r"(a[0]), "r"(a[1]), "r"(a[2]), "r"(a[3]), "r"(b[0]), "r"(b[1]));
}

template<int MODE>
__global__ __launch_bounds__(256) void gemm_bf16(const __nv_bfloat16* __restrict__ A,
                                                 const __nv_bfloat16* __restrict__ Bm,
                                                 float* __restrict__ out)
{
    __shared__ __align__(16) __nv_bfloat16 sA[128][SAS];
    __shared__ __align__(16) __nv_bfloat16 sB[128][SAS];

    const int tid  = threadIdx.x;
    const int wid  = tid >> 5, lane = tid & 31;
    const int m0   = blockIdx.y * 128, n0 = blockIdx.x * 128;
    const int wm   = (wid & 3) * 32;
    const int wn   = (wid >> 2) * 64;
    const int tq   = lane & 3;    // quad
    const int tg   = lane >> 2;   // group 0..7

    float c[2][8][4];
    #pragma unroll
    for (int mb = 0; mb < 2; mb++)
        #pragma unroll
        for (int nb = 0; nb < 8; nb++)
            #pragma unroll
            for (int i = 0; i < 4; i++) c[mb][nb][i] = 0.f;

    for (int kc = 0; kc < K2; kc += 32) {
        #pragma unroll
        for (int it = 0; it < 2; it++) {
            int idx = tid + it * 256;          // 0..511
            int r   = idx >> 2;                // 0..127
            int c8  = (idx & 3) << 3;          // 0,8,16,24
            *(uint4*)&sA[r][c8] = *(const uint4*)(A  + (size_t)(m0 + r) * K2 + kc + c8);
            *(uint4*)&sB[r][c8] = *(const uint4*)(Bm + (size_t)(n0 + r) * K2 + kc + c8);
        }
        __syncthreads();

        #pragma unroll
        for (int ks = 0; ks < 32; ks += 16) {
            uint32_t af[2][4], bf[8][2];
            #pragma unroll
            for (int mb = 0; mb < 2; mb++) {
                int r = wm + mb * 16 + tg;
                af[mb][0] = *(const uint32_t*)&sA[r    ][ks + tq * 2    ];
                af[mb][1] = *(const uint32_t*)&sA[r + 8][ks + tq * 2    ];
                af[mb][2] = *(const uint32_t*)&sA[r    ][ks + tq * 2 + 8];
                af[mb][3] = *(const uint32_t*)&sA[r + 8][ks + tq * 2 + 8];
            }
            #pragma unroll
            for (int nb = 0; nb < 8; nb++) {
                int r = wn + nb * 8 + tg;
                bf[nb][0] = *(const uint32_t*)&sB[r][ks + tq * 2    ];
                bf[nb][1] = *(const uint32_t*)&sB[r][ks + tq * 2 + 8];
            }
            #pragma unroll
            for (int mb = 0; mb < 2; mb++)
                #pragma unroll
                for (int nb = 0; nb < 8; nb++)
                    mma_bf16(c[mb][nb], af[mb], bf[nb]);
        }
        __syncthreads();
    }

    // Epilogue: c0,c1 at (m, n..n+1); c2,c3 at (m+8, n..n+1)
    #pragma unroll
    for (int mb = 0; mb < 2; mb++) {
        #pragma unroll
        for (int nb = 0; nb < 8; nb++) {
            const int m = m0 + wm + mb * 16 + tg;
            const int n = n0 + wn + nb * 8 + tq * 2;
            if (MODE == 0) {
                const int b = m >> 12, t = m & 4095;
                const int h = n >> 6,  d = n & 63;
                float* p = out + (((size_t)(b * H_ + h)) * T_ + t) * D_ + d;
                *(float2*)p              = make_float2(c[mb][nb][0], c[mb][nb][1]);
                *(float2*)(p + 8 * D_)   = make_float2(c[mb][nb][2], c[mb][nb][3]);
            } else {
                float* p = out + (size_t)m * C_ + n;
                *(float2*)p              = make_float2(c[mb][nb][0], c[mb][nb][1]);
                *(float2*)(p + 8 * C_)   = make_float2(c[mb][nb][2], c[mb][nb][3]);
            }
        }
    }
}

// ---------------------------------------------------------------------------
// Causal flash attention (register-blocked SIMT, unchanged from R2).
// ---------------------------------------------------------------------------
#define AS 68
#define ATTN_SMEM (4 * 64 * AS * 4)

__global__ __launch_bounds__(256, 2) void attn_fwd(const float* __restrict__ Q,
                                                   const float* __restrict__ K,
                                                   const float* __restrict__ V,
                                                   float* __restrict__ ctx)
{
    extern __shared__ float sm[];
    float* Qt = sm;                // [64][AS]  Qt[d][r]
    float* Kt = sm + 64 * AS;      // [64][AS]  Kt[d][j]
    float* Vs = sm + 2 * 64 * AS;  // [64][AS]  Vs[j][d]
    float* Ps = sm + 3 * 64 * AS;  // [64][AS]  Ps[j][r]

    const int tid = threadIdx.x;
    const int tr  = tid >> 4;
    const int tc  = tid & 15;
    const int qt  = blockIdx.x;
    const int bh  = blockIdx.y;
    const size_t base_bh = (size_t)bh * T_ * D_;

    {
        const float* src = Q + base_bh + (size_t)qt * 64 * D_;
        #pragma unroll
        for (int it = 0; it < 4; it++) {
            int lin = tid + it * 256;
            int r   = lin >> 4;
            int c4  = (lin & 15) << 2;
            float4 qv = *(const float4*)(src + r * 64 + c4);
            Qt[(c4 + 0) * AS + r] = qv.x;
            Qt[(c4 + 1) * AS + r] = qv.y;
            Qt[(c4 + 2) * AS + r] = qv.z;
            Qt[(c4 + 3) * AS + r] = qv.w;
        }
    }

    float O[4][4];
    #pragma unroll
    for (int i = 0; i < 4; i++)
        #pragma unroll
        for (int j = 0; j < 4; j++) O[i][j] = 0.f;
    float m_i[4], l_i[4];
    #pragma unroll
    for (int i = 0; i < 4; i++) { m_i[i] = -1e30f; l_i[i] = 0.f; }

    for (int kt = 0; kt <= qt; kt++) {
        __syncthreads();
        {
            const float* ksrc = K + base_bh + (size_t)kt * 64 * D_;
            const float* vsrc = V + base_bh + (size_t)kt * 64 * D_;
            #pragma unroll
            for (int it = 0; it < 4; it++) {
                int lin = tid + it * 256;
                int r   = lin >> 4;
                int c4  = (lin & 15) << 2;
                float4 kv = *(const float4*)(ksrc + r * 64 + c4);
                Kt[(c4 + 0) * AS + r] = kv.x;
                Kt[(c4 + 1) * AS + r] = kv.y;
                Kt[(c4 + 2) * AS + r] = kv.z;
                Kt[(c4 + 3) * AS + r] = kv.w;
                *(float4*)(Vs + r * AS + c4) = *(const float4*)(vsrc + r * 64 + c4);
            }
        }
        __syncthreads();

        float S[4][4];
        #pragma unroll
        for (int i = 0; i < 4; i++)
            #pragma unroll
            for (int j = 0; j < 4; j++) S[i][j] = 0.f;

        #pragma unroll 8
        for (int d = 0; d < 64; d++) {
            float4 a = *(const float4*)(Qt + d * AS + tr * 4);
            float4 b = *(const float4*)(Kt + d * AS + tc * 4);
            S[0][0] += a.x * b.x; S[0][1] += a.x * b.y; S[0][2] += a.x * b.z; S[0][3] += a.x * b.w;
            S[1][0] += a.y * b.x; S[1][1] += a.y * b.y; S[1][2] += a.y * b.z; S[1][3] += a.y * b.w;
            S[2][0] += a.z * b.x; S[2][1] += a.z * b.y; S[2][2] += a.z * b.z; S[2][3] += a.z * b.w;
            S[3][0] += a.w * b.x; S[3][1] += a.w * b.y; S[3][2] += a.w * b.z; S[3][3] += a.w * b.w;
        }

        const float scale = 0.125f;
        if (kt == qt) {
            #pragma unroll
            for (int i = 0; i < 4; i++)
                #pragma unroll
                for (int j = 0; j < 4; j++)
                    S[i][j] = (tc * 4 + j <= tr * 4 + i) ? S[i][j] * scale : -1e30f;
        } else {
            #pragma unroll
            for (int i = 0; i < 4; i++)
                #pragma unroll
                for (int j = 0; j < 4; j++) S[i][j] *= scale;
        }

        float P[4][4];
        #pragma unroll
        for (int i = 0; i < 4; i++) {
            float mx = fmaxf(fmaxf(S[i][0], S[i][1]), fmaxf(S[i][2], S[i][3]));
            mx = fmaxf(mx, __shfl_xor_sync(0xffffffffu, mx, 1));
            mx = fmaxf(mx, __shfl_xor_sync(0xffffffffu, mx, 2));
            mx = fmaxf(mx, __shfl_xor_sync(0xffffffffu, mx, 4));
            mx = fmaxf(mx, __shfl_xor_sync(0xffffffffu, mx, 8));
            const float m_new = fmaxf(m_i[i], mx);
            const float corr  = __expf(m_i[i] - m_new);
            float ps = 0.f;
            #pragma unroll
            for (int j = 0; j < 4; j++) { P[i][j] = __expf(S[i][j] - m_new); ps += P[i][j]; }
            ps += __shfl_xor_sync(0xffffffffu, ps, 1);
            ps += __shfl_xor_sync(0xffffffffu, ps, 2);
            ps += __shfl_xor_sync(0xffffffffu, ps, 4);
            ps += __shfl_xor_sync(0xffffffffu, ps, 8);
            l_i[i] = l_i[i] * corr + ps;
            m_i[i] = m_new;
            #pragma unroll
            for (int j = 0; j < 4; j++) O[i][j] *= corr;
        }

        #pragma unroll
        for (int jc = 0; jc < 4; jc++) {
            *(float4*)(Ps + (tc * 4 + jc) * AS + tr * 4) =
                make_float4(P[0][jc], P[1][jc], P[2][jc], P[3][jc]);
        }
        __syncthreads();

        #pragma unroll 8
        for (int j = 0; j < 64; j++) {
            float4 p = *(const float4*)(Ps + j * AS + tr * 4);
            float4 v = *(const float4*)(Vs + j * AS + tc * 4);
            O[0][0] += p.x * v.x; O[0][1] += p.x * v.y; O[0][2] += p.x * v.z; O[0][3] += p.x * v.w;
            O[1][0] += p.y * v.x; O[1][1] += p.y * v.y; O[1][2] += p.y * v.z; O[1][3] += p.y * v.w;
            O[2][0] += p.z * v.x; O[2][1] += p.z * v.y; O[2][2] += p.z * v.z; O[2][3] += p.z * v.w;
            O[3][0] += p.w * v.x; O[3][1] += p.w * v.y; O[3][2] += p.w * v.z; O[3][3] += p.w * v.w;
        }
    }

    const int b = bh / H_, h = bh % H_;
    #pragma unroll
    for (int i = 0; i < 4; i++) {
        const float inv = 1.f / l_i[i];
        const int trow = qt * 64 + tr * 4 + i;
        float4 o = make_float4(O[i][0] * inv, O[i][1] * inv, O[i][2] * inv, O[i][3] * inv);
        *(float4*)(ctx + ((size_t)b * T_ + trow) * C_ + h * 64 + tc * 4) = o;
    }
}

// ---------------------------------------------------------------------------
extern "C" void kernel_launch(void* const* d_in, const int* in_sizes, int n_in,
                              void* d_out, int out_size)
{
    (void)in_sizes; (void)n_in; (void)out_size;
    const float* x  = (const float*)d_in[0];
    const float* wq = (const float*)d_in[1];
    const float* wk = (const float*)d_in[2];
    const float* wv = (const float*)d_in[3];
    const float* wo = (const float*)d_in[4];
    float* out = (float*)d_out;

    float *q, *k, *v, *ctx;
    __nv_bfloat16 *x2, *ctx2, *wq2, *wk2, *wv2, *wo2;
    cudaGetSymbolAddress((void**)&q,    g_q);
    cudaGetSymbolAddress((void**)&k,    g_k);
    cudaGetSymbolAddress((void**)&v,    g_v);
    cudaGetSymbolAddress((void**)&ctx,  g_ctx);
    cudaGetSymbolAddress((void**)&x2,   g_x2);
    cudaGetSymbolAddress((void**)&ctx2, g_ctx2);
    cudaGetSymbolAddress((void**)&wq2,  g_wq2);
    cudaGetSymbolAddress((void**)&wk2,  g_wk2);
    cudaGetSymbolAddress((void**)&wv2,  g_wv2);
    cudaGetSymbolAddress((void**)&wo2,  g_wo2);

    const int nx = BT_ * C_;
    const int nw = C_ * C_;
    conv_hilo<0><<<(nx + 255) / 256, 256>>>(x,  x2,  nx);
    conv_hilo<1><<<(nw + 255) / 256, 256>>>(wq, wq2, nw);
    conv_hilo<1><<<(nw + 255) / 256, 256>>>(wk, wk2, nw);
    conv_hilo<1><<<(nw + 255) / 256, 256>>>(wv, wv2, nw);
    conv_hilo<1><<<(nw + 255) / 256, 256>>>(wo, wo2, nw);

    const dim3 ggrid(C_ / 128, BT_ / 128);
    gemm_bf16<0><<<ggrid, 256>>>(x2, wq2, q);
    gemm_bf16<0><<<ggrid, 256>>>(x2, wk2, k);
    gemm_bf16<0><<<ggrid, 256>>>(x2, wv2, v);

    cudaFuncSetAttribute(attn_fwd, cudaFuncAttributeMaxDynamicSharedMemorySize, ATTN_SMEM);
    attn_fwd<<<dim3(T_ / 64, B_ * H_), 256, ATTN_SMEM>>>(q, k, v, ctx);

    conv_hilo<0><<<(nx + 255) / 256, 256>>>(ctx, ctx2, nx);
    gemm_bf16<1><<<ggrid, 256>>>(ctx2, wo2, out);
}

// round 8
// speedup vs baseline: 3.3422x; 1.7545x over previous
#include <cuda_runtime.h>
#include <cuda_bf16.h>
#include <cstdint>
#include <math.h>

#define B_ 2
#define T_ 4096
#define H_ 12
#define D_ 64
#define C_ 768
#define BT_ (B_*T_)
#define BH_ (B_*H_)
#define K2 2304   // 3 * C_ : [hi | lo | hi] x [hi | hi | lo]
#define D2 192    // 3 * D_ for attention QK split

// Scratch (static device globals — allocation-free per harness rules)
__device__ float g_q[(size_t)BH_*T_*D_];
__device__ float g_k[(size_t)BH_*T_*D_];
__device__ float g_v[(size_t)BH_*T_*D_];
__device__ float g_ctx[(size_t)BT_*C_];
__device__ __nv_bfloat16 g_x2[(size_t)BT_*K2];
__device__ __nv_bfloat16 g_ctx2[(size_t)BT_*K2];
__device__ __nv_bfloat16 g_wq2[(size_t)C_*K2];
__device__ __nv_bfloat16 g_wk2[(size_t)C_*K2];
__device__ __nv_bfloat16 g_wv2[(size_t)C_*K2];
__device__ __nv_bfloat16 g_wo2[(size_t)C_*K2];
__device__ __nv_bfloat16 g_q2[(size_t)BH_*T_*D2];
__device__ __nv_bfloat16 g_k2[(size_t)BH_*T_*D2];
__device__ uint32_t g_vph[(size_t)BH_*(T_/2)*D_];
__device__ uint32_t g_vpl[(size_t)BH_*(T_/2)*D_];

// ---------------------------------------------------------------------------
// fp32 -> compensated bf16 split, K-concatenated (projection GEMM operands).
// ---------------------------------------------------------------------------
template<int ISW>
__global__ __launch_bounds__(256) void conv_hilo(const float* __restrict__ in,
                                                 __nv_bfloat16* __restrict__ out,
                                                 int nelem)
{
    int idx = blockIdx.x * 256 + threadIdx.x;
    if (idx >= nelem) return;
    int r = idx / C_, c = idx % C_;
    float x = in[idx];
    __nv_bfloat16 hi = __float2bfloat16(x);
    __nv_bfloat16 lo = __float2bfloat16(x - __bfloat162float(hi));
    __nv_bfloat16* o = out + (size_t)r * K2;
    if (ISW) { o[c] = hi; o[c + C_] = hi; o[c + 2*C_] = lo; }
    else     { o[c] = hi; o[c + C_] = lo; o[c + 2*C_] = hi; }
}

// Q/K fp32 (BH,T,64) -> split bf16 (BH,T,192). ORD=0: [hi|lo|hi], ORD=1: [hi|hi|lo]
template<int ORD>
__global__ __launch_bounds__(256) void conv_qk(const float* __restrict__ in,
                                               __nv_bfloat16* __restrict__ out,
                                               int nelem)
{
    int idx = blockIdx.x * 256 + threadIdx.x;
    if (idx >= nelem) return;
    int r = idx >> 6, c = idx & 63;
    float x = in[idx];
    __nv_bfloat16 hi = __float2bfloat16(x);
    __nv_bfloat16 lo = __float2bfloat16(x - __bfloat162float(hi));
    __nv_bfloat16* o = out + (size_t)r * D2;
    if (ORD) { o[c] = hi; o[c + 64] = hi; o[c + 128] = lo; }
    else     { o[c] = hi; o[c + 64] = lo; o[c + 128] = hi; }
}

// V fp32 (BH,T,64) -> packed key-pair bf16: vph/vpl (BH, T/2, 64) uint32
__global__ __launch_bounds__(256) void conv_vp(const float* __restrict__ in,
                                               uint32_t* __restrict__ vph,
                                               uint32_t* __restrict__ vpl,
                                               int nelem)  // BH*(T/2)*64
{
    int idx = blockIdx.x * 256 + threadIdx.x;
    if (idx >= nelem) return;
    int d  = idx & 63;
    int t2 = idx >> 6;          // global pair index across BH*T/2
    float v0 = in[(size_t)(2*t2) * 64 + d];
    float v1 = in[(size_t)(2*t2) * 64 + 64 + d];
    __nv_bfloat16 h0 = __float2bfloat16(v0);
    __nv_bfloat16 h1 = __float2bfloat16(v1);
    __nv_bfloat16 l0 = __float2bfloat16(v0 - __bfloat162float(h0));
    __nv_bfloat16 l1 = __float2bfloat16(v1 - __bfloat162float(h1));
    __nv_bfloat162 hp = __halves2bfloat162(h0, h1);   // .x low = key 2t2
    __nv_bfloat162 lp = __halves2bfloat162(l0, l1);
    vph[idx] = *(uint32_t*)&hp;
    vpl[idx] = *(uint32_t*)&lp;
}

// ---------------------------------------------------------------------------
// bf16 HMMA NT GEMM (projections): unchanged from R7.
// ---------------------------------------------------------------------------
#define SAS 40

__device__ __forceinline__ void mma_bf16(float c[4], const uint32_t a[4], const uint32_t b[2])
{
    asm volatile(
        "mma.sync.aligned.m16n8k16.row.col.f32.bf16.bf16.f32 "
        "{%0,%1,%2,%3}, {%4,%5,%6,%7}, {%8,%9}, {%0,%1,%2,%3};"
        : "+f"(c[0]), "+f"(c[1]), "+f"(c[2]), "+f"(c[3])
        : "r"(a[0]), "r"(a[1]), "r"(a[2]), "r"(a[3]), "r"(b[0]), "r"(b[1]));
}

template<int MODE>
__global__ __launch_bounds__(256) void gemm_bf16(const __nv_bfloat16* __restrict__ A,
                                                 const __nv_bfloat16* __restrict__ Bm,
                                                 float* __restrict__ out)
{
    __shared__ __align__(16) __nv_bfloat16 sA[128][SAS];
    __shared__ __align__(16) __nv_bfloat16 sB[128][SAS];

    const int tid  = threadIdx.x;
    const int wid  = tid >> 5, lane = tid & 31;
    const int m0   = blockIdx.y * 128, n0 = blockIdx.x * 128;
    const int wm   = (wid & 3) * 32;
    const int wn   = (wid >> 2) * 64;
    const int tq   = lane & 3;
    const int tg   = lane >> 2;

    float c[2][8][4];
    #pragma unroll
    for (int mb = 0; mb < 2; mb++)
        #pragma unroll
        for (int nb = 0; nb < 8; nb++)
            #pragma unroll
            for (int i = 0; i < 4; i++) c[mb][nb][i] = 0.f;

    for (int kc = 0; kc < K2; kc += 32) {
        #pragma unroll
        for (int it = 0; it < 2; it++) {
            int idx = tid + it * 256;
            int r   = idx >> 2;
            int c8  = (idx & 3) << 3;
            *(uint4*)&sA[r][c8] = *(const uint4*)(A  + (size_t)(m0 + r) * K2 + kc + c8);
            *(uint4*)&sB[r][c8] = *(const uint4*)(Bm + (size_t)(n0 + r) * K2 + kc + c8);
        }
        __syncthreads();

        #pragma unroll
        for (int ks = 0; ks < 32; ks += 16) {
            uint32_t af[2][4], bf[8][2];
            #pragma unroll
            for (int mb = 0; mb < 2; mb++) {
                int r = wm + mb * 16 + tg;
                af[mb][0] = *(const uint32_t*)&sA[r    ][ks + tq * 2    ];
                af[mb][1] = *(const uint32_t*)&sA[r + 8][ks + tq * 2    ];
                af[mb][2] = *(const uint32_t*)&sA[r    ][ks + tq * 2 + 8];
                af[mb][3] = *(const uint32_t*)&sA[r + 8][ks + tq * 2 + 8];
            }
            #pragma unroll
            for (int nb = 0; nb < 8; nb++) {
                int r = wn + nb * 8 + tg;
                bf[nb][0] = *(const uint32_t*)&sB[r][ks + tq * 2    ];
                bf[nb][1] = *(const uint32_t*)&sB[r][ks + tq * 2 + 8];
            }
            #pragma unroll
            for (int mb = 0; mb < 2; mb++)
                #pragma unroll
                for (int nb = 0; nb < 8; nb++)
                    mma_bf16(c[mb][nb], af[mb], bf[nb]);
        }
        __syncthreads();
    }

    #pragma unroll
    for (int mb = 0; mb < 2; mb++) {
        #pragma unroll
        for (int nb = 0; nb < 8; nb++) {
            const int m = m0 + wm + mb * 16 + tg;
            const int n = n0 + wn + nb * 8 + tq * 2;
            if (MODE == 0) {
                const int b = m >> 12, t = m & 4095;
                const int h = n >> 6,  d = n & 63;
                float* p = out + (((size_t)(b * H_ + h)) * T_ + t) * D_ + d;
                *(float2*)p              = make_float2(c[mb][nb][0], c[mb][nb][1]);
                *(float2*)(p + 8 * D_)   = make_float2(c[mb][nb][2], c[mb][nb][3]);
            } else {
                float* p = out + (size_t)m * C_ + n;
                *(float2*)p              = make_float2(c[mb][nb][0], c[mb][nb][1]);
                *(float2*)(p + 8 * C_)   = make_float2(c[mb][nb][2], c[mb][nb][3]);
            }
        }
    }
}

// ---------------------------------------------------------------------------
// HMMA causal flash attention.
// CTA: 128 query rows for one bh. 8 warps x 16 rows (m16). Key tiles of 64.
// QK over D2=192 (split), S in fp32 frags, online softmax in frag layout,
// P hi/lo in registers, PV = Phi*Vhi + Plo*Vhi + Phi*Vlo.
// smem strides (uint32): sQ/sK rows 100 (96 data), sV rows 72 (64 data):
// fragment LDS bank = (4*tg+tq) / (8*tq+tg) -> conflict-free.
// ---------------------------------------------------------------------------
#define SQS 100
#define SVS 72
#define ATTN_SMEM ((128*SQS + 64*SQS + 64*SVS) * 4)   // 95232 B

__global__ __launch_bounds__(256, 1) void attn_mma(const __nv_bfloat16* __restrict__ Q2,
                                                   const __nv_bfloat16* __restrict__ Ksp,
                                                   const uint32_t* __restrict__ Vph,
                                                   const uint32_t* __restrict__ Vpl,
                                                   float* __restrict__ ctx)
{
    extern __shared__ uint32_t smem_u[];
    uint32_t* sQ = smem_u;                    // [128][SQS]
    uint32_t* sK = smem_u + 128 * SQS;        // [64][SQS]
    uint32_t* sV = smem_u + 128 * SQS + 64 * SQS;  // [64][SVS] rows 0-31 hi, 32-63 lo

    const int tid = threadIdx.x;
    const int w   = tid >> 5;
    const int lane = tid & 31;
    const int tg  = lane >> 2;
    const int tq  = lane & 3;
    const int qt  = blockIdx.x;
    const int bh  = blockIdx.y;
    const int qb  = qt * 128;
    const int rbase = qb + w * 16;
    const int row0 = rbase + tg;
    const int row1 = row0 + 8;

    // Load Q2 tile (128 x 192 halves) into sQ
    {
        const __nv_bfloat16* qsrc = Q2 + ((size_t)bh * T_ + qb) * D2;
        int r = tid >> 1;
        #pragma unroll
        for (int i = 0; i < 12; i++) {
            int c4 = (tid & 1) + 2 * i;   // uint4 col 0..23
            *(uint4*)(sQ + r * SQS + c4 * 4) = *(const uint4*)(qsrc + (size_t)r * D2 + c4 * 8);
        }
    }

    float O[8][4];
    #pragma unroll
    for (int nb = 0; nb < 8; nb++)
        #pragma unroll
        for (int i = 0; i < 4; i++) O[nb][i] = 0.f;
    float m0 = -1e30f, m1 = -1e30f, l0 = 0.f, l1 = 0.f;

    const int nkt = 2 * qt + 2;
    for (int kt = 0; kt < nkt; kt++) {
        const int ktbase = kt * 64;
        __syncthreads();
        {   // load K tile (64 x 192 halves) + V tile (64 x 64 uint32)
            int r  = tid >> 2;
            int cb = tid & 3;
            const __nv_bfloat16* ksrc = Ksp + ((size_t)bh * T_ + ktbase + r) * D2;
            #pragma unroll
            for (int i = 0; i < 6; i++) {
                int c4 = cb + 4 * i;
                *(uint4*)(sK + r * SQS + c4 * 4) = *(const uint4*)(ksrc + c4 * 8);
            }
            const uint32_t* vsrc = (r < 32)
                ? Vph + ((size_t)bh * (T_/2) + ktbase/2 + r) * 64
                : Vpl + ((size_t)bh * (T_/2) + ktbase/2 + (r - 32)) * 64;
            #pragma unroll
            for (int i = 0; i < 4; i++) {
                int c4 = cb + 4 * i;
                *(uint4*)(sV + r * SVS + c4 * 4) = *(const uint4*)(vsrc + c4 * 4);
            }
        }
        __syncthreads();

        if (ktbase > rbase + 15) continue;   // warp entirely above this key tile

        // ---- S = Q K^T over 12 k-steps (D2=192) ----
        float S[8][4];
        #pragma unroll
        for (int nb = 0; nb < 8; nb++)
            #pragma unroll
            for (int i = 0; i < 4; i++) S[nb][i] = 0.f;

        #pragma unroll
        for (int ks = 0; ks < 12; ks++) {
            uint32_t a[4];
            a[0] = sQ[(w*16 + tg    ) * SQS + ks*8 + tq    ];
            a[1] = sQ[(w*16 + tg + 8) * SQS + ks*8 + tq    ];
            a[2] = sQ[(w*16 + tg    ) * SQS + ks*8 + tq + 4];
            a[3] = sQ[(w*16 + tg + 8) * SQS + ks*8 + tq + 4];
            #pragma unroll
            for (int nb = 0; nb < 8; nb++) {
                uint32_t b[2];
                b[0] = sK[(nb*8 + tg) * SQS + ks*8 + tq    ];
                b[1] = sK[(nb*8 + tg) * SQS + ks*8 + tq + 4];
                mma_bf16(S[nb], a, b);
            }
        }

        #pragma unroll
        for (int nb = 0; nb < 8; nb++)
            #pragma unroll
            for (int i = 0; i < 4; i++) S[nb][i] *= 0.125f;

        if (ktbase + 63 > rbase) {   // causal mask (only near-diagonal tiles)
            #pragma unroll
            for (int nb = 0; nb < 8; nb++) {
                int col0 = ktbase + nb*8 + 2*tq;
                int col1 = col0 + 1;
                if (col0 > row0) S[nb][0] = -1e30f;
                if (col1 > row0) S[nb][1] = -1e30f;
                if (col0 > row1) S[nb][2] = -1e30f;
                if (col1 > row1) S[nb][3] = -1e30f;
            }
        }

        // ---- online softmax (rows row0=tg, row1=tg+8; quad lanes share row) ----
        float mx0 = -1e30f, mx1 = -1e30f;
        #pragma unroll
        for (int nb = 0; nb < 8; nb++) {
            mx0 = fmaxf(mx0, fmaxf(S[nb][0], S[nb][1]));
            mx1 = fmaxf(mx1, fmaxf(S[nb][2], S[nb][3]));
        }
        mx0 = fmaxf(mx0, __shfl_xor_sync(0xffffffffu, mx0, 1));
        mx0 = fmaxf(mx0, __shfl_xor_sync(0xffffffffu, mx0, 2));
        mx1 = fmaxf(mx1, __shfl_xor_sync(0xffffffffu, mx1, 1));
        mx1 = fmaxf(mx1, __shfl_xor_sync(0xffffffffu, mx1, 2));

        const float m0n = fmaxf(m0, mx0);
        const float m1n = fmaxf(m1, mx1);
        const float cr0 = __expf(m0 - m0n);
        const float cr1 = __expf(m1 - m1n);

        uint32_t phi0[8], phi1[8], plo0[8], plo1[8];
        float ps0 = 0.f, ps1 = 0.f;
        #pragma unroll
        for (int nb = 0; nb < 8; nb++) {
            float p00 = __expf(S[nb][0] - m0n);
            float p01 = __expf(S[nb][1] - m0n);
            float p10 = __expf(S[nb][2] - m1n);
            float p11 = __expf(S[nb][3] - m1n);
            ps0 += p00 + p01;
            ps1 += p10 + p11;
            __nv_bfloat162 h0 = __float22bfloat162_rn(make_float2(p00, p01));
            __nv_bfloat162 h1 = __float22bfloat162_rn(make_float2(p10, p11));
            phi0[nb] = *(uint32_t*)&h0;
            phi1[nb] = *(uint32_t*)&h1;
            __nv_bfloat162 e0 = __float22bfloat162_rn(make_float2(
                p00 - __bfloat162float(h0.x), p01 - __bfloat162float(h0.y)));
            __nv_bfloat162 e1 = __float22bfloat162_rn(make_float2(
                p10 - __bfloat162float(h1.x), p11 - __bfloat162float(h1.y)));
            plo0[nb] = *(uint32_t*)&e0;
            plo1[nb] = *(uint32_t*)&e1;
        }
        ps0 += __shfl_xor_sync(0xffffffffu, ps0, 1);
        ps0 += __shfl_xor_sync(0xffffffffu, ps0, 2);
        ps1 += __shfl_xor_sync(0xffffffffu, ps1, 1);
        ps1 += __shfl_xor_sync(0xffffffffu, ps1, 2);
        l0 = l0 * cr0 + ps0;  m0 = m0n;
        l1 = l1 * cr1 + ps1;  m1 = m1n;
        #pragma unroll
        for (int nb = 0; nb < 8; nb++) {
            O[nb][0] *= cr0; O[nb][1] *= cr0;
            O[nb][2] *= cr1; O[nb][3] *= cr1;
        }

        // ---- PV: O += Phi*Vhi + Plo*Vhi + Phi*Vlo ----
        #pragma unroll
        for (int ks = 0; ks < 4; ks++) {
            uint32_t ahi[4] = { phi0[2*ks], phi1[2*ks], phi0[2*ks+1], phi1[2*ks+1] };
            uint32_t alo[4] = { plo0[2*ks], plo1[2*ks], plo0[2*ks+1], plo1[2*ks+1] };
            #pragma unroll
            for (int nb = 0; nb < 8; nb++) {
                uint32_t bhv[2];
                bhv[0] = sV[(ks*8 + tq    ) * SVS + nb*8 + tg];
                bhv[1] = sV[(ks*8 + tq + 4) * SVS + nb*8 + tg];
                mma_bf16(O[nb], ahi, bhv);
                mma_bf16(O[nb], alo, bhv);
            }
            #pragma unroll
            for (int nb = 0; nb < 8; nb++) {
                uint32_t blv[2];
                blv[0] = sV[(32 + ks*8 + tq    ) * SVS + nb*8 + tg];
                blv[1] = sV[(32 + ks*8 + tq + 4) * SVS + nb*8 + tg];
                mma_bf16(O[nb], ahi, blv);
            }
        }
    }

    // ---- epilogue: normalize, write ctx (B, T, C) ----
    const float inv0 = 1.f / l0;
    const float inv1 = 1.f / l1;
    const int b = bh / H_, h = bh % H_;
    #pragma unroll
    for (int nb = 0; nb < 8; nb++) {
        const int d = nb * 8 + 2 * tq;
        *(float2*)(ctx + ((size_t)b * T_ + row0) * C_ + h * 64 + d) =
            make_float2(O[nb][0] * inv0, O[nb][1] * inv0);
        *(float2*)(ctx + ((size_t)b * T_ + row1) * C_ + h * 64 + d) =
            make_float2(O[nb][2] * inv1, O[nb][3] * inv1);
    }
}

// ---------------------------------------------------------------------------
extern "C" void kernel_launch(void* const* d_in, const int* in_sizes, int n_in,
                              void* d_out, int out_size)
{
    (void)in_sizes; (void)n_in; (void)out_size;
    const float* x  = (const float*)d_in[0];
    const float* wq = (const float*)d_in[1];
    const float* wk = (const float*)d_in[2];
    const float* wv = (const float*)d_in[3];
    const float* wo = (const float*)d_in[4];
    float* out = (float*)d_out;

    float *q, *k, *v, *ctx;
    __nv_bfloat16 *x2, *ctx2, *wq2, *wk2, *wv2, *wo2, *q2, *k2;
    uint32_t *vph, *vpl;
    cudaGetSymbolAddress((void**)&q,    g_q);
    cudaGetSymbolAddress((void**)&k,    g_k);
    cudaGetSymbolAddress((void**)&v,    g_v);
    cudaGetSymbolAddress((void**)&ctx,  g_ctx);
    cudaGetSymbolAddress((void**)&x2,   g_x2);
    cudaGetSymbolAddress((void**)&ctx2, g_ctx2);
    cudaGetSymbolAddress((void**)&wq2,  g_wq2);
    cudaGetSymbolAddress((void**)&wk2,  g_wk2);
    cudaGetSymbolAddress((void**)&wv2,  g_wv2);
    cudaGetSymbolAddress((void**)&wo2,  g_wo2);
    cudaGetSymbolAddress((void**)&q2,   g_q2);
    cudaGetSymbolAddress((void**)&k2,   g_k2);
    cudaGetSymbolAddress((void**)&vph,  g_vph);
    cudaGetSymbolAddress((void**)&vpl,  g_vpl);

    const int nx = BT_ * C_;
    const int nw = C_ * C_;
    conv_hilo<0><<<(nx + 255) / 256, 256>>>(x,  x2,  nx);
    conv_hilo<1><<<(nw + 255) / 256, 256>>>(wq, wq2, nw);
    conv_hilo<1><<<(nw + 255) / 256, 256>>>(wk, wk2, nw);
    conv_hilo<1><<<(nw + 255) / 256, 256>>>(wv, wv2, nw);
    conv_hilo<1><<<(nw + 255) / 256, 256>>>(wo, wo2, nw);

    const dim3 ggrid(C_ / 128, BT_ / 128);
    gemm_bf16<0><<<ggrid, 256>>>(x2, wq2, q);
    gemm_bf16<0><<<ggrid, 256>>>(x2, wk2, k);
    gemm_bf16<0><<<ggrid, 256>>>(x2, wv2, v);

    const int nqk = BH_ * T_ * D_;
    const int nvp = BH_ * (T_/2) * D_;
    conv_qk<0><<<(nqk + 255) / 256, 256>>>(q, q2, nqk);
    conv_qk<1><<<(nqk + 255) / 256, 256>>>(k, k2, nqk);
    conv_vp<<<(nvp + 255) / 256, 256>>>(v, vph, vpl, nvp);

    cudaFuncSetAttribute(attn_mma, cudaFuncAttributeMaxDynamicSharedMemorySize, ATTN_SMEM);
    attn_mma<<<dim3(T_ / 128, BH_), 256, ATTN_SMEM>>>(q2, k2, vph, vpl, ctx);

    conv_hilo<0><<<(nx + 255) / 256, 256>>>(ctx, ctx2, nx);
    gemm_bf16<1><<<ggrid, 256>>>(ctx2, wo2, out);
}

// round 9
// speedup vs baseline: 3.8783x; 1.1604x over previous
#include <cuda_runtime.h>
#include <cuda_bf16.h>
#include <cstdint>
#include <math.h>

#define B_ 2
#define T_ 4096
#define H_ 12
#define D_ 64
#define C_ 768
#define BT_ (B_*T_)
#define BH_ (B_*H_)
#define K2 2304   // 3 * C_ : [hi | lo | hi] x [hi | hi | lo]
#define D2 192    // 3 * D_ for attention QK split

// Scratch (static device globals — allocation-free per harness rules)
__device__ float g_v[(size_t)BH_*T_*D_];
__device__ float g_ctx[(size_t)BT_*C_];
__device__ __nv_bfloat16 g_x2[(size_t)BT_*K2];
__device__ __nv_bfloat16 g_ctx2[(size_t)BT_*K2];
__device__ __nv_bfloat16 g_wq2[(size_t)C_*K2];
__device__ __nv_bfloat16 g_wk2[(size_t)C_*K2];
__device__ __nv_bfloat16 g_wv2[(size_t)C_*K2];
__device__ __nv_bfloat16 g_wo2[(size_t)C_*K2];
__device__ __nv_bfloat16 g_q2[(size_t)BH_*T_*D2];
__device__ __nv_bfloat16 g_k2[(size_t)BH_*T_*D2];
__device__ uint32_t g_vph[(size_t)BH_*(T_/2)*D_];
__device__ uint32_t g_vpl[(size_t)BH_*(T_/2)*D_];

// ---------------------------------------------------------------------------
// fp32 -> compensated bf16 split, K-concatenated (projection GEMM operands).
// ---------------------------------------------------------------------------
template<int ISW>
__global__ __launch_bounds__(256) void conv_hilo(const float* __restrict__ in,
                                                 __nv_bfloat16* __restrict__ out,
                                                 int nelem)
{
    int idx = blockIdx.x * 256 + threadIdx.x;
    if (idx >= nelem) return;
    int r = idx / C_, c = idx % C_;
    float x = in[idx];
    __nv_bfloat16 hi = __float2bfloat16(x);
    __nv_bfloat16 lo = __float2bfloat16(x - __bfloat162float(hi));
    __nv_bfloat16* o = out + (size_t)r * K2;
    if (ISW) { o[c] = hi; o[c + C_] = hi; o[c + 2*C_] = lo; }
    else     { o[c] = hi; o[c + C_] = lo; o[c + 2*C_] = hi; }
}

// V fp32 (BH,T,64) -> packed key-pair bf16: vph/vpl (BH, T/2, 64) uint32
__global__ __launch_bounds__(256) void conv_vp(const float* __restrict__ in,
                                               uint32_t* __restrict__ vph,
                                               uint32_t* __restrict__ vpl,
                                               int nelem)  // BH*(T/2)*64
{
    int idx = blockIdx.x * 256 + threadIdx.x;
    if (idx >= nelem) return;
    int d  = idx & 63;
    int t2 = idx >> 6;          // global pair index across BH*T/2
    float v0 = in[(size_t)(2*t2) * 64 + d];
    float v1 = in[(size_t)(2*t2) * 64 + 64 + d];
    __nv_bfloat16 h0 = __float2bfloat16(v0);
    __nv_bfloat16 h1 = __float2bfloat16(v1);
    __nv_bfloat16 l0 = __float2bfloat16(v0 - __bfloat162float(h0));
    __nv_bfloat16 l1 = __float2bfloat16(v1 - __bfloat162float(h1));
    __nv_bfloat162 hp = __halves2bfloat162(h0, h1);
    __nv_bfloat162 lp = __halves2bfloat162(l0, l1);
    vph[idx] = *(uint32_t*)&hp;
    vpl[idx] = *(uint32_t*)&lp;
}

// ---------------------------------------------------------------------------
// cp.async helpers
// ---------------------------------------------------------------------------
__device__ __forceinline__ void cp16(void* dst, const void* src)
{
    uint32_t d = (uint32_t)__cvta_generic_to_shared(dst);
    asm volatile("cp.async.cg.shared.global [%0], [%1], 16;\n" :: "r"(d), "l"(src));
}
__device__ __forceinline__ void cp_commit()  { asm volatile("cp.async.commit_group;\n" ::: "memory"); }
__device__ __forceinline__ void cp_wait1()   { asm volatile("cp.async.wait_group 1;\n" ::: "memory"); }
__device__ __forceinline__ void cp_wait0()   { asm volatile("cp.async.wait_group 0;\n" ::: "memory"); }

// ---------------------------------------------------------------------------
// bf16 HMMA NT GEMM, cp.async 2-stage pipeline.
// out(M x 768) = A2(M x K2) @ B2(768 x K2)^T, fp32 accum.
// CTA 128x128, 8 warps 4(m)x2(n), warp tile 32x64, mma m16n8k16, 2 CTAs/SM.
// MODE 0: fp32 scatter to (B,H,T,D).      MODE 1: fp32 row-major (M,768).
// MODE 2: split [hi|lo|hi] to (BH,T,192). MODE 3: split [hi|hi|lo] to (BH,T,192).
// ---------------------------------------------------------------------------
#define SAS 40
#define NKC (K2/32)   // 72

__device__ __forceinline__ void mma_bf16(float c[4], const uint32_t a[4], const uint32_t b[2])
{
    asm volatile(
        "mma.sync.aligned.m16n8k16.row.col.f32.bf16.bf16.f32 "
        "{%0,%1,%2,%3}, {%4,%5,%6,%7}, {%8,%9}, {%0,%1,%2,%3};"
        : "+f"(c[0]), "+f"(c[1]), "+f"(c[2]), "+f"(c[3])
        : "r"(a[0]), "r"(a[1]), "r"(a[2]), "r"(a[3]), "r"(b[0]), "r"(b[1]));
}

template<int MODE>
__global__ __launch_bounds__(256, 2) void gemm_bf16(const __nv_bfloat16* __restrict__ A,
                                                    const __nv_bfloat16* __restrict__ Bm,
                                                    void* __restrict__ outv)
{
    __shared__ __align__(16) __nv_bfloat16 sA[2][128][SAS];
    __shared__ __align__(16) __nv_bfloat16 sB[2][128][SAS];

    const int tid  = threadIdx.x;
    const int wid  = tid >> 5, lane = tid & 31;
    const int m0   = blockIdx.y * 128, n0 = blockIdx.x * 128;
    const int wm   = (wid & 3) * 32;
    const int wn   = (wid >> 2) * 64;
    const int tq   = lane & 3;
    const int tg   = lane >> 2;

    const int lr  = tid >> 2;          // 0..63   (stage-fill row helper: 2 rows apart)
    const int lc8 = (tid & 3) << 3;    // 0,8,16,24

    float c[2][8][4];
    #pragma unroll
    for (int mb = 0; mb < 2; mb++)
        #pragma unroll
        for (int nb = 0; nb < 8; nb++)
            #pragma unroll
            for (int i = 0; i < 4; i++) c[mb][nb][i] = 0.f;

    // stage fill: 4 cp16 per thread per matrix half (rows lr and lr+64)
    auto issue = [&](int kc, int s) {
        #pragma unroll
        for (int half = 0; half < 2; half++) {
            int r = lr + half * 64;
            cp16(&sA[s][r][lc8], A  + (size_t)(m0 + r) * K2 + kc * 32 + lc8);
            cp16(&sB[s][r][lc8], Bm + (size_t)(n0 + r) * K2 + kc * 32 + lc8);
        }
    };

    issue(0, 0);
    cp_commit();

    for (int kc = 0; kc < NKC; kc++) {
        const int s = kc & 1;
        if (kc + 1 < NKC) { issue(kc + 1, s ^ 1); cp_commit(); cp_wait1(); }
        else              { cp_wait0(); }
        __syncthreads();

        #pragma unroll
        for (int ks = 0; ks < 32; ks += 16) {
            uint32_t af[2][4], bf[8][2];
            #pragma unroll
            for (int mb = 0; mb < 2; mb++) {
                int r = wm + mb * 16 + tg;
                af[mb][0] = *(const uint32_t*)&sA[s][r    ][ks + tq * 2    ];
                af[mb][1] = *(const uint32_t*)&sA[s][r + 8][ks + tq * 2    ];
                af[mb][2] = *(const uint32_t*)&sA[s][r    ][ks + tq * 2 + 8];
                af[mb][3] = *(const uint32_t*)&sA[s][r + 8][ks + tq * 2 + 8];
            }
            #pragma unroll
            for (int nb = 0; nb < 8; nb++) {
                int r = wn + nb * 8 + tg;
                bf[nb][0] = *(const uint32_t*)&sB[s][r][ks + tq * 2    ];
                bf[nb][1] = *(const uint32_t*)&sB[s][r][ks + tq * 2 + 8];
            }
            #pragma unroll
            for (int mb = 0; mb < 2; mb++)
                #pragma unroll
                for (int nb = 0; nb < 8; nb++)
                    mma_bf16(c[mb][nb], af[mb], bf[nb]);
        }
        __syncthreads();
    }

    // ---- epilogue ----
    #pragma unroll
    for (int mb = 0; mb < 2; mb++) {
        #pragma unroll
        for (int nb = 0; nb < 8; nb++) {
            const int m = m0 + wm + mb * 16 + tg;
            const int n = n0 + wn + nb * 8 + tq * 2;
            if (MODE == 0) {
                float* out = (float*)outv;
                const int b = m >> 12, t = m & 4095;
                const int h = n >> 6,  d = n & 63;
                float* p = out + (((size_t)(b * H_ + h)) * T_ + t) * D_ + d;
                *(float2*)p            = make_float2(c[mb][nb][0], c[mb][nb][1]);
                *(float2*)(p + 8 * D_) = make_float2(c[mb][nb][2], c[mb][nb][3]);
            } else if (MODE == 1) {
                float* out = (float*)outv;
                float* p = out + (size_t)m * C_ + n;
                *(float2*)p            = make_float2(c[mb][nb][0], c[mb][nb][1]);
                *(float2*)(p + 8 * C_) = make_float2(c[mb][nb][2], c[mb][nb][3]);
            } else {
                // split epilogue into (BH, T, D2)
                __nv_bfloat16* out = (__nv_bfloat16*)outv;
                const int b = m >> 12, t = m & 4095;
                const int h = n >> 6,  d = n & 63;
                #pragma unroll
                for (int half = 0; half < 2; half++) {
                    const float v0 = c[mb][nb][2*half + 0];
                    const float v1 = c[mb][nb][2*half + 1];
                    __nv_bfloat16 h0 = __float2bfloat16(v0);
                    __nv_bfloat16 h1 = __float2bfloat16(v1);
                    __nv_bfloat16 e0 = __float2bfloat16(v0 - __bfloat162float(h0));
                    __nv_bfloat16 e1 = __float2bfloat16(v1 - __bfloat162float(h1));
                    __nv_bfloat162 hp = __halves2bfloat162(h0, h1);
                    __nv_bfloat162 ep = __halves2bfloat162(e0, e1);
                    __nv_bfloat16* p = out + ((size_t)(b * H_ + h) * T_ + t + half * 8) * D2 + d;
                    if (MODE == 2) {   // Q: [hi | lo | hi]
                        *(__nv_bfloat162*)(p)       = hp;
                        *(__nv_bfloat162*)(p + 64)  = ep;
                        *(__nv_bfloat162*)(p + 128) = hp;
                    } else {           // K: [hi | hi | lo]
                        *(__nv_bfloat162*)(p)       = hp;
                        *(__nv_bfloat162*)(p + 64)  = hp;
                        *(__nv_bfloat162*)(p + 128) = ep;
                    }
                }
            }
        }
    }
}

// ---------------------------------------------------------------------------
// HMMA causal flash attention (unchanged from R8).
// ---------------------------------------------------------------------------
#define SQS 100
#define SVS 72
#define ATTN_SMEM ((128*SQS + 64*SQS + 64*SVS) * 4)   // 95232 B

__global__ __launch_bounds__(256, 1) void attn_mma(const __nv_bfloat16* __restrict__ Q2,
                                                   const __nv_bfloat16* __restrict__ Ksp,
                                                   const uint32_t* __restrict__ Vph,
                                                   const uint32_t* __restrict__ Vpl,
                                                   float* __restrict__ ctx)
{
    extern __shared__ uint32_t smem_u[];
    uint32_t* sQ = smem_u;                    // [128][SQS]
    uint32_t* sK = smem_u + 128 * SQS;        // [64][SQS]
    uint32_t* sV = smem_u + 128 * SQS + 64 * SQS;  // [64][SVS] rows 0-31 hi, 32-63 lo

    const int tid = threadIdx.x;
    const int w   = tid >> 5;
    const int lane = tid & 31;
    const int tg  = lane >> 2;
    const int tq  = lane & 3;
    const int qt  = blockIdx.x;
    const int bh  = blockIdx.y;
    const int qb  = qt * 128;
    const int rbase = qb + w * 16;
    const int row0 = rbase + tg;
    const int row1 = row0 + 8;

    {
        const __nv_bfloat16* qsrc = Q2 + ((size_t)bh * T_ + qb) * D2;
        int r = tid >> 1;
        #pragma unroll
        for (int i = 0; i < 12; i++) {
            int c4 = (tid & 1) + 2 * i;
            *(uint4*)(sQ + r * SQS + c4 * 4) = *(const uint4*)(qsrc + (size_t)r * D2 + c4 * 8);
        }
    }

    float O[8][4];
    #pragma unroll
    for (int nb = 0; nb < 8; nb++)
        #pragma unroll
        for (int i = 0; i < 4; i++) O[nb][i] = 0.f;
    float m0 = -1e30f, m1 = -1e30f, l0 = 0.f, l1 = 0.f;

    const int nkt = 2 * qt + 2;
    for (int kt = 0; kt < nkt; kt++) {
        const int ktbase = kt * 64;
        __syncthreads();
        {
            int r  = tid >> 2;
            int cb = tid & 3;
            const __nv_bfloat16* ksrc = Ksp + ((size_t)bh * T_ + ktbase + r) * D2;
            #pragma unroll
            for (int i = 0; i < 6; i++) {
                int c4 = cb + 4 * i;
                *(uint4*)(sK + r * SQS + c4 * 4) = *(const uint4*)(ksrc + c4 * 8);
            }
            const uint32_t* vsrc = (r < 32)
                ? Vph + ((size_t)bh * (T_/2) + ktbase/2 + r) * 64
                : Vpl + ((size_t)bh * (T_/2) + ktbase/2 + (r - 32)) * 64;
            #pragma unroll
            for (int i = 0; i < 4; i++) {
                int c4 = cb + 4 * i;
                *(uint4*)(sV + r * SVS + c4 * 4) = *(const uint4*)(vsrc + c4 * 4);
            }
        }
        __syncthreads();

        if (ktbase > rbase + 15) continue;

        float S[8][4];
        #pragma unroll
        for (int nb = 0; nb < 8; nb++)
            #pragma unroll
            for (int i = 0; i < 4; i++) S[nb][i] = 0.f;

        #pragma unroll
        for (int ks = 0; ks < 12; ks++) {
            uint32_t a[4];
            a[0] = sQ[(w*16 + tg    ) * SQS + ks*8 + tq    ];
            a[1] = sQ[(w*16 + tg + 8) * SQS + ks*8 + tq    ];
            a[2] = sQ[(w*16 + tg    ) * SQS + ks*8 + tq + 4];
            a[3] = sQ[(w*16 + tg + 8) * SQS + ks*8 + tq + 4];
            #pragma unroll
            for (int nb = 0; nb < 8; nb++) {
                uint32_t b[2];
                b[0] = sK[(nb*8 + tg) * SQS + ks*8 + tq    ];
                b[1] = sK[(nb*8 + tg) * SQS + ks*8 + tq + 4];
                mma_bf16(S[nb], a, b);
            }
        }

        #pragma unroll
        for (int nb = 0; nb < 8; nb++)
            #pragma unroll
            for (int i = 0; i < 4; i++) S[nb][i] *= 0.125f;

        if (ktbase + 63 > rbase) {
            #pragma unroll
            for (int nb = 0; nb < 8; nb++) {
                int col0 = ktbase + nb*8 + 2*tq;
                int col1 = col0 + 1;
                if (col0 > row0) S[nb][0] = -1e30f;
                if (col1 > row0) S[nb][1] = -1e30f;
                if (col0 > row1) S[nb][2] = -1e30f;
                if (col1 > row1) S[nb][3] = -1e30f;
            }
        }

        float mx0 = -1e30f, mx1 = -1e30f;
        #pragma unroll
        for (int nb = 0; nb < 8; nb++) {
            mx0 = fmaxf(mx0, fmaxf(S[nb][0], S[nb][1]));
            mx1 = fmaxf(mx1, fmaxf(S[nb][2], S[nb][3]));
        }
        mx0 = fmaxf(mx0, __shfl_xor_sync(0xffffffffu, mx0, 1));
        mx0 = fmaxf(mx0, __shfl_xor_sync(0xffffffffu, mx0, 2));
        mx1 = fmaxf(mx1, __shfl_xor_sync(0xffffffffu, mx1, 1));
        mx1 = fmaxf(mx1, __shfl_xor_sync(0xffffffffu, mx1, 2));

        const float m0n = fmaxf(m0, mx0);
        const float m1n = fmaxf(m1, mx1);
        const float cr0 = __expf(m0 - m0n);
        const float cr1 = __expf(m1 - m1n);

        uint32_t phi0[8], phi1[8], plo0[8], plo1[8];
        float ps0 = 0.f, ps1 = 0.f;
        #pragma unroll
        for (int nb = 0; nb < 8; nb++) {
            float p00 = __expf(S[nb][0] - m0n);
            float p01 = __expf(S[nb][1] - m0n);
            float p10 = __expf(S[nb][2] - m1n);
            float p11 = __expf(S[nb][3] - m1n);
            ps0 += p00 + p01;
            ps1 += p10 + p11;
            __nv_bfloat162 h0 = __float22bfloat162_rn(make_float2(p00, p01));
            __nv_bfloat162 h1 = __float22bfloat162_rn(make_float2(p10, p11));
            phi0[nb] = *(uint32_t*)&h0;
            phi1[nb] = *(uint32_t*)&h1;
            __nv_bfloat162 e0 = __float22bfloat162_rn(make_float2(
                p00 - __bfloat162float(h0.x), p01 - __bfloat162float(h0.y)));
            __nv_bfloat162 e1 = __float22bfloat162_rn(make_float2(
                p10 - __bfloat162float(h1.x), p11 - __bfloat162float(h1.y)));
            plo0[nb] = *(uint32_t*)&e0;
            plo1[nb] = *(uint32_t*)&e1;
        }
        ps0 += __shfl_xor_sync(0xffffffffu, ps0, 1);
        ps0 += __shfl_xor_sync(0xffffffffu, ps0, 2);
        ps1 += __shfl_xor_sync(0xffffffffu, ps1, 1);
        ps1 += __shfl_xor_sync(0xffffffffu, ps1, 2);
        l0 = l0 * cr0 + ps0;  m0 = m0n;
        l1 = l1 * cr1 + ps1;  m1 = m1n;
        #pragma unroll
        for (int nb = 0; nb < 8; nb++) {
            O[nb][0] *= cr0; O[nb][1] *= cr0;
            O[nb][2] *= cr1; O[nb][3] *= cr1;
        }

        #pragma unroll
        for (int ks = 0; ks < 4; ks++) {
            uint32_t ahi[4] = { phi0[2*ks], phi1[2*ks], phi0[2*ks+1], phi1[2*ks+1] };
            uint32_t alo[4] = { plo0[2*ks], plo1[2*ks], plo0[2*ks+1], plo1[2*ks+1] };
            #pragma unroll
            for (int nb = 0; nb < 8; nb++) {
                uint32_t bhv[2];
                bhv[0] = sV[(ks*8 + tq    ) * SVS + nb*8 + tg];
                bhv[1] = sV[(ks*8 + tq + 4) * SVS + nb*8 + tg];
                mma_bf16(O[nb], ahi, bhv);
                mma_bf16(O[nb], alo, bhv);
            }
            #pragma unroll
            for (int nb = 0; nb < 8; nb++) {
                uint32_t blv[2];
                blv[0] = sV[(32 + ks*8 + tq    ) * SVS + nb*8 + tg];
                blv[1] = sV[(32 + ks*8 + tq + 4) * SVS + nb*8 + tg];
                mma_bf16(O[nb], ahi, blv);
            }
        }
    }

    const float inv0 = 1.f / l0;
    const float inv1 = 1.f / l1;
    const int b = bh / H_, h = bh % H_;
    #pragma unroll
    for (int nb = 0; nb < 8; nb++) {
        const int d = nb * 8 + 2 * tq;
        *(float2*)(ctx + ((size_t)b * T_ + row0) * C_ + h * 64 + d) =
            make_float2(O[nb][0] * inv0, O[nb][1] * inv0);
        *(float2*)(ctx + ((size_t)b * T_ + row1) * C_ + h * 64 + d) =
            make_float2(O[nb][2] * inv1, O[nb][3] * inv1);
    }
}

// ---------------------------------------------------------------------------
extern "C" void kernel_launch(void* const* d_in, const int* in_sizes, int n_in,
                              void* d_out, int out_size)
{
    (void)in_sizes; (void)n_in; (void)out_size;
    const float* x  = (const float*)d_in[0];
    const float* wq = (const float*)d_in[1];
    const float* wk = (const float*)d_in[2];
    const float* wv = (const float*)d_in[3];
    const float* wo = (const float*)d_in[4];
    float* out = (float*)d_out;

    float *v, *ctx;
    __nv_bfloat16 *x2, *ctx2, *wq2, *wk2, *wv2, *wo2, *q2, *k2;
    uint32_t *vph, *vpl;
    cudaGetSymbolAddress((void**)&v,    g_v);
    cudaGetSymbolAddress((void**)&ctx,  g_ctx);
    cudaGetSymbolAddress((void**)&x2,   g_x2);
    cudaGetSymbolAddress((void**)&ctx2, g_ctx2);
    cudaGetSymbolAddress((void**)&wq2,  g_wq2);
    cudaGetSymbolAddress((void**)&wk2,  g_wk2);
    cudaGetSymbolAddress((void**)&wv2,  g_wv2);
    cudaGetSymbolAddress((void**)&wo2,  g_wo2);
    cudaGetSymbolAddress((void**)&q2,   g_q2);
    cudaGetSymbolAddress((void**)&k2,   g_k2);
    cudaGetSymbolAddress((void**)&vph,  g_vph);
    cudaGetSymbolAddress((void**)&vpl,  g_vpl);

    const int nx = BT_ * C_;
    const int nw = C_ * C_;
    conv_hilo<0><<<(nx + 255) / 256, 256>>>(x,  x2,  nx);
    conv_hilo<1><<<(nw + 255) / 256, 256>>>(wq, wq2, nw);
    conv_hilo<1><<<(nw + 255) / 256, 256>>>(wk, wk2, nw);
    conv_hilo<1><<<(nw + 255) / 256, 256>>>(wv, wv2, nw);
    conv_hilo<1><<<(nw + 255) / 256, 256>>>(wo, wo2, nw);

    const dim3 ggrid(C_ / 128, BT_ / 128);
    gemm_bf16<2><<<ggrid, 256>>>(x2, wq2, q2);   // Q: split [hi|lo|hi]
    gemm_bf16<3><<<ggrid, 256>>>(x2, wk2, k2);   // K: split [hi|hi|lo]
    gemm_bf16<0><<<ggrid, 256>>>(x2, wv2, v);    // V: fp32 (B,H,T,D)

    const int nvp = BH_ * (T_/2) * D_;
    conv_vp<<<(nvp + 255) / 256, 256>>>(v, vph, vpl, nvp);

    cudaFuncSetAttribute(attn_mma, cudaFuncAttributeMaxDynamicSharedMemorySize, ATTN_SMEM);
    attn_mma<<<dim3(T_ / 128, BH_), 256, ATTN_SMEM>>>(q2, k2, vph, vpl, ctx);

    conv_hilo<0><<<(nx + 255) / 256, 256>>>(ctx, ctx2, nx);
    gemm_bf16<1><<<ggrid, 256>>>(ctx2, wo2, out);
}

// round 12
// speedup vs baseline: 3.9122x; 1.0087x over previous
#include <cuda_runtime.h>
#include <cuda_bf16.h>
#include <cstdint>
#include <math.h>

#define B_ 2
#define T_ 4096
#define H_ 12
#define D_ 64
#define C_ 768
#define BT_ (B_*T_)
#define BH_ (B_*H_)
#define K2 2304   // 3 * C_ : [hi | lo | hi] x [hi | hi | lo]
#define D2 192    // 3 * D_ for attention QK split
#define N3 2304   // merged QKV output width (3 * 768)

// Scratch (static device globals — allocation-free per harness rules)
__device__ float g_v[(size_t)BH_*T_*D_];
__device__ float g_ctx[(size_t)BT_*C_];
__device__ __nv_bfloat16 g_x2[(size_t)BT_*K2];
__device__ __nv_bfloat16 g_ctx2[(size_t)BT_*K2];
__device__ __nv_bfloat16 g_wqkv2[(size_t)N3*K2];   // rows 0..767 wq, 768..1535 wk, 1536..2303 wv
__device__ __nv_bfloat16 g_wo2[(size_t)C_*K2];
__device__ __nv_bfloat16 g_q2[(size_t)BH_*T_*D2];
__device__ __nv_bfloat16 g_k2[(size_t)BH_*T_*D2];
__device__ uint32_t g_vph[(size_t)BH_*(T_/2)*D_];
__device__ uint32_t g_vpl[(size_t)BH_*(T_/2)*D_];

// ---------------------------------------------------------------------------
// fp32 -> compensated bf16 split, K-concatenated (projection GEMM operands).
// ---------------------------------------------------------------------------
template<int ISW>
__global__ __launch_bounds__(256) void conv_hilo(const float* __restrict__ in,
                                                 __nv_bfloat16* __restrict__ out,
                                                 int nelem)
{
    int idx = blockIdx.x * 256 + threadIdx.x;
    if (idx >= nelem) return;
    int r = idx / C_, c = idx % C_;
    float x = in[idx];
    __nv_bfloat16 hi = __float2bfloat16(x);
    __nv_bfloat16 lo = __float2bfloat16(x - __bfloat162float(hi));
    __nv_bfloat16* o = out + (size_t)r * K2;
    if (ISW) { o[c] = hi; o[c + C_] = hi; o[c + 2*C_] = lo; }
    else     { o[c] = hi; o[c + C_] = lo; o[c + 2*C_] = hi; }
}

// V fp32 (BH,T,64) -> packed key-pair bf16: vph/vpl (BH, T/2, 64) uint32
__global__ __launch_bounds__(256) void conv_vp(const float* __restrict__ in,
                                               uint32_t* __restrict__ vph,
                                               uint32_t* __restrict__ vpl,
                                               int nelem)  // BH*(T/2)*64
{
    int idx = blockIdx.x * 256 + threadIdx.x;
    if (idx >= nelem) return;
    int d  = idx & 63;
    int t2 = idx >> 6;
    float v0 = in[(size_t)(2*t2) * 64 + d];
    float v1 = in[(size_t)(2*t2) * 64 + 64 + d];
    __nv_bfloat16 h0 = __float2bfloat16(v0);
    __nv_bfloat16 h1 = __float2bfloat16(v1);
    __nv_bfloat16 l0 = __float2bfloat16(v0 - __bfloat162float(h0));
    __nv_bfloat16 l1 = __float2bfloat16(v1 - __bfloat162float(h1));
    __nv_bfloat162 hp = __halves2bfloat162(h0, h1);
    __nv_bfloat162 lp = __halves2bfloat162(l0, l1);
    vph[idx] = *(uint32_t*)&hp;
    vpl[idx] = *(uint32_t*)&lp;
}

// ---------------------------------------------------------------------------
// cp.async helpers
// ---------------------------------------------------------------------------
__device__ __forceinline__ void cp16(void* dst, const void* src)
{
    uint32_t d = (uint32_t)__cvta_generic_to_shared(dst);
    asm volatile("cp.async.cg.shared.global [%0], [%1], 16;\n" :: "r"(d), "l"(src));
}
__device__ __forceinline__ void cp_commit()  { asm volatile("cp.async.commit_group;\n" ::: "memory"); }
__device__ __forceinline__ void cp_wait1()   { asm volatile("cp.async.wait_group 1;\n" ::: "memory"); }
__device__ __forceinline__ void cp_wait0()   { asm volatile("cp.async.wait_group 0;\n" ::: "memory"); }

// ---------------------------------------------------------------------------
// bf16 HMMA NT GEMM, cp.async 2-stage pipeline.
// MODE 1: O-GEMM, NT=64 tile, fp32 row-major (M,768) out.
// MODE 4: merged QKV, NT=128, epilogue by section (Q-split / K-split / V-fp32).
// ---------------------------------------------------------------------------
#define SAS 40
#define NKC (K2/32)   // 72

__device__ __forceinline__ void mma_bf16(float c[4], const uint32_t a[4], const uint32_t b[2])
{
    asm volatile(
        "mma.sync.aligned.m16n8k16.row.col.f32.bf16.bf16.f32 "
        "{%0,%1,%2,%3}, {%4,%5,%6,%7}, {%8,%9}, {%0,%1,%2,%3};"
        : "+f"(c[0]), "+f"(c[1]), "+f"(c[2]), "+f"(c[3])
        : "r"(a[0]), "r"(a[1]), "r"(a[2]), "r"(a[3]), "r"(b[0]), "r"(b[1]));
}

template<int MODE>
__global__ __launch_bounds__(256, 2) void gemm_bf16(const __nv_bfloat16* __restrict__ A,
                                                    const __nv_bfloat16* __restrict__ Bm,
                                                    void* __restrict__ outv,
                                                    void* __restrict__ outv2,
                                                    void* __restrict__ outv3)
{
    constexpr int NT = (MODE == 1) ? 64 : 128;    // CTA n-tile
    constexpr int NB = (MODE == 1) ? 4  : 8;      // per-warp n-blocks

    __shared__ __align__(16) __nv_bfloat16 sA[2][128][SAS];
    __shared__ __align__(16) __nv_bfloat16 sB[2][NT][SAS];

    const int tid  = threadIdx.x;
    const int wid  = tid >> 5, lane = tid & 31;
    const int m0   = blockIdx.y * 128, n0 = blockIdx.x * NT;
    const int wm   = (wid & 3) * 32;
    const int wn   = (wid >> 2) * (NT / 2);
    const int tq   = lane & 3;
    const int tg   = lane >> 2;

    const int lr  = tid >> 2;          // 0..63
    const int lc8 = (tid & 3) << 3;    // 0,8,16,24

    float c[2][NB][4];
    #pragma unroll
    for (int mb = 0; mb < 2; mb++)
        #pragma unroll
        for (int nb = 0; nb < NB; nb++)
            #pragma unroll
            for (int i = 0; i < 4; i++) c[mb][nb][i] = 0.f;

    auto issue = [&](int kc, int s) {
        #pragma unroll
        for (int half = 0; half < 2; half++) {
            int r = lr + half * 64;
            cp16(&sA[s][r][lc8], A + (size_t)(m0 + r) * K2 + kc * 32 + lc8);
        }
        if (NT == 128) {
            #pragma unroll
            for (int half = 0; half < 2; half++) {
                int r = lr + half * 64;
                cp16(&sB[s][r][lc8], Bm + (size_t)(n0 + r) * K2 + kc * 32 + lc8);
            }
        } else {
            cp16(&sB[s][lr][lc8], Bm + (size_t)(n0 + lr) * K2 + kc * 32 + lc8);
        }
    };

    issue(0, 0);
    cp_commit();

    for (int kc = 0; kc < NKC; kc++) {
        const int s = kc & 1;
        if (kc + 1 < NKC) { issue(kc + 1, s ^ 1); cp_commit(); cp_wait1(); }
        else              { cp_wait0(); }
        __syncthreads();

        #pragma unroll
        for (int ks = 0; ks < 32; ks += 16) {
            uint32_t af[2][4], bf[NB][2];
            #pragma unroll
            for (int mb = 0; mb < 2; mb++) {
                int r = wm + mb * 16 + tg;
                af[mb][0] = *(const uint32_t*)&sA[s][r    ][ks + tq * 2    ];
                af[mb][1] = *(const uint32_t*)&sA[s][r + 8][ks + tq * 2    ];
                af[mb][2] = *(const uint32_t*)&sA[s][r    ][ks + tq * 2 + 8];
                af[mb][3] = *(const uint32_t*)&sA[s][r + 8][ks + tq * 2 + 8];
            }
            #pragma unroll
            for (int nb = 0; nb < NB; nb++) {
                int r = wn + nb * 8 + tg;
                bf[nb][0] = *(const uint32_t*)&sB[s][r][ks + tq * 2    ];
                bf[nb][1] = *(const uint32_t*)&sB[s][r][ks + tq * 2 + 8];
            }
            #pragma unroll
            for (int mb = 0; mb < 2; mb++)
                #pragma unroll
                for (int nb = 0; nb < NB; nb++)
                    mma_bf16(c[mb][nb], af[mb], bf[nb]);
        }
        __syncthreads();
    }

    // ---- epilogue ----
    #pragma unroll
    for (int mb = 0; mb < 2; mb++) {
        #pragma unroll
        for (int nb = 0; nb < NB; nb++) {
            const int m = m0 + wm + mb * 16 + tg;
            const int n = n0 + wn + nb * 8 + tq * 2;
            if (MODE == 1) {
                float* out = (float*)outv;
                float* p = out + (size_t)m * C_ + n;
                *(float2*)p            = make_float2(c[mb][nb][0], c[mb][nb][1]);
                *(float2*)(p + 8 * C_) = make_float2(c[mb][nb][2], c[mb][nb][3]);
            } else {
                // merged QKV: section 0 = Q-split, 1 = K-split, 2 = V fp32
                const int sec  = n / 768;           // uniform within CTA
                const int nloc = n - sec * 768;
                const int b = m >> 12, t = m & 4095;
                const int h = nloc >> 6, d = nloc & 63;
                if (sec == 2) {
                    float* out = (float*)outv3;     // V fp32 (BH,T,D)
                    float* p = out + (((size_t)(b * H_ + h)) * T_ + t) * D_ + d;
                    *(float2*)p            = make_float2(c[mb][nb][0], c[mb][nb][1]);
                    *(float2*)(p + 8 * D_) = make_float2(c[mb][nb][2], c[mb][nb][3]);
                } else {
                    __nv_bfloat16* out = (sec == 0) ? (__nv_bfloat16*)outv
                                                    : (__nv_bfloat16*)outv2;
                    #pragma unroll
                    for (int half = 0; half < 2; half++) {
                        const float v0 = c[mb][nb][2*half + 0];
                        const float v1 = c[mb][nb][2*half + 1];
                        __nv_bfloat16 h0 = __float2bfloat16(v0);
                        __nv_bfloat16 h1 = __float2bfloat16(v1);
                        __nv_bfloat16 e0 = __float2bfloat16(v0 - __bfloat162float(h0));
                        __nv_bfloat16 e1 = __float2bfloat16(v1 - __bfloat162float(h1));
                        __nv_bfloat162 hp = __halves2bfloat162(h0, h1);
                        __nv_bfloat162 ep = __halves2bfloat162(e0, e1);
                        __nv_bfloat16* p = out + ((size_t)(b * H_ + h) * T_ + t + half * 8) * D2 + d;
                        if (sec == 0) {   // Q: [hi | lo | hi]
                            *(__nv_bfloat162*)(p)       = hp;
                            *(__nv_bfloat162*)(p + 64)  = ep;
                            *(__nv_bfloat162*)(p + 128) = hp;
                        } else {          // K: [hi | hi | lo]
                            *(__nv_bfloat162*)(p)       = hp;
                            *(__nv_bfloat162*)(p + 64)  = hp;
                            *(__nv_bfloat162*)(p + 128) = ep;
                        }
                    }
                }
            }
        }
    }
}

// ---------------------------------------------------------------------------
// HMMA causal flash attention (unchanged from R8).
// ---------------------------------------------------------------------------
#define SQS 100
#define SVS 72
#define ATTN_SMEM ((128*SQS + 64*SQS + 64*SVS) * 4)   // 95232 B

__global__ __launch_bounds__(256, 1) void attn_mma(const __nv_bfloat16* __restrict__ Q2,
                                                   const __nv_bfloat16* __restrict__ Ksp,
                                                   const uint32_t* __restrict__ Vph,
                                                   const uint32_t* __restrict__ Vpl,
                                                   float* __restrict__ ctx)
{
    extern __shared__ uint32_t smem_u[];
    uint32_t* sQ = smem_u;
    uint32_t* sK = smem_u + 128 * SQS;
    uint32_t* sV = smem_u + 128 * SQS + 64 * SQS;

    const int tid = threadIdx.x;
    const int w   = tid >> 5;
    const int lane = tid & 31;
    const int tg  = lane >> 2;
    const int tq  = lane & 3;
    const int qt  = blockIdx.x;
    const int bh  = blockIdx.y;
    const int qb  = qt * 128;
    const int rbase = qb + w * 16;
    const int row0 = rbase + tg;
    const int row1 = row0 + 8;

    {
        const __nv_bfloat16* qsrc = Q2 + ((size_t)bh * T_ + qb) * D2;
        int r = tid >> 1;
        #pragma unroll
        for (int i = 0; i < 12; i++) {
            int c4 = (tid & 1) + 2 * i;
            *(uint4*)(sQ + r * SQS + c4 * 4) = *(const uint4*)(qsrc + (size_t)r * D2 + c4 * 8);
        }
    }

    float O[8][4];
    #pragma unroll
    for (int nb = 0; nb < 8; nb++)
        #pragma unroll
        for (int i = 0; i < 4; i++) O[nb][i] = 0.f;
    float m0 = -1e30f, m1 = -1e30f, l0 = 0.f, l1 = 0.f;

    const int nkt = 2 * qt + 2;
    for (int kt = 0; kt < nkt; kt++) {
        const int ktbase = kt * 64;
        __syncthreads();
        {
            int r  = tid >> 2;
            int cb = tid & 3;
            const __nv_bfloat16* ksrc = Ksp + ((size_t)bh * T_ + ktbase + r) * D2;
            #pragma unroll
            for (int i = 0; i < 6; i++) {
                int c4 = cb + 4 * i;
                *(uint4*)(sK + r * SQS + c4 * 4) = *(const uint4*)(ksrc + c4 * 8);
            }
            const uint32_t* vsrc = (r < 32)
                ? Vph + ((size_t)bh * (T_/2) + ktbase/2 + r) * 64
                : Vpl + ((size_t)bh * (T_/2) + ktbase/2 + (r - 32)) * 64;
            #pragma unroll
            for (int i = 0; i < 4; i++) {
                int c4 = cb + 4 * i;
                *(uint4*)(sV + r * SVS + c4 * 4) = *(const uint4*)(vsrc + c4 * 4);
            }
        }
        __syncthreads();

        if (ktbase > rbase + 15) continue;

        float S[8][4];
        #pragma unroll
        for (int nb = 0; nb < 8; nb++)
            #pragma unroll
            for (int i = 0; i < 4; i++) S[nb][i] = 0.f;

        #pragma unroll
        for (int ks = 0; ks < 12; ks++) {
            uint32_t a[4];
            a[0] = sQ[(w*16 + tg    ) * SQS + ks*8 + tq    ];
            a[1] = sQ[(w*16 + tg + 8) * SQS + ks*8 + tq    ];
            a[2] = sQ[(w*16 + tg    ) * SQS + ks*8 + tq + 4];
            a[3] = sQ[(w*16 + tg + 8) * SQS + ks*8 + tq + 4];
            #pragma unroll
            for (int nb = 0; nb < 8; nb++) {
                uint32_t b[2];
                b[0] = sK[(nb*8 + tg) * SQS + ks*8 + tq    ];
                b[1] = sK[(nb*8 + tg) * SQS + ks*8 + tq + 4];
                mma_bf16(S[nb], a, b);
            }
        }

        #pragma unroll
        for (int nb = 0; nb < 8; nb++)
            #pragma unroll
            for (int i = 0; i < 4; i++) S[nb][i] *= 0.125f;

        if (ktbase + 63 > rbase) {
            #pragma unroll
            for (int nb = 0; nb < 8; nb++) {
                int col0 = ktbase + nb*8 + 2*tq;
                int col1 = col0 + 1;
                if (col0 > row0) S[nb][0] = -1e30f;
                if (col1 > row0) S[nb][1] = -1e30f;
                if (col0 > row1) S[nb][2] = -1e30f;
                if (col1 > row1) S[nb][3] = -1e30f;
            }
        }

        float mx0 = -1e30f, mx1 = -1e30f;
        #pragma unroll
        for (int nb = 0; nb < 8; nb++) {
            mx0 = fmaxf(mx0, fmaxf(S[nb][0], S[nb][1]));
            mx1 = fmaxf(mx1, fmaxf(S[nb][2], S[nb][3]));
        }
        mx0 = fmaxf(mx0, __shfl_xor_sync(0xffffffffu, mx0, 1));
        mx0 = fmaxf(mx0, __shfl_xor_sync(0xffffffffu, mx0, 2));
        mx1 = fmaxf(mx1, __shfl_xor_sync(0xffffffffu, mx1, 1));
        mx1 = fmaxf(mx1, __shfl_xor_sync(0xffffffffu, mx1, 2));

        const float m0n = fmaxf(m0, mx0);
        const float m1n = fmaxf(m1, mx1);
        const float cr0 = __expf(m0 - m0n);
        const float cr1 = __expf(m1 - m1n);

        uint32_t phi0[8], phi1[8], plo0[8], plo1[8];
        float ps0 = 0.f, ps1 = 0.f;
        #pragma unroll
        for (int nb = 0; nb < 8; nb++) {
            float p00 = __expf(S[nb][0] - m0n);
            float p01 = __expf(S[nb][1] - m0n);
            float p10 = __expf(S[nb][2] - m1n);
            float p11 = __expf(S[nb][3] - m1n);
            ps0 += p00 + p01;
            ps1 += p10 + p11;
            __nv_bfloat162 h0 = __float22bfloat162_rn(make_float2(p00, p01));
            __nv_bfloat162 h1 = __float22bfloat162_rn(make_float2(p10, p11));
            phi0[nb] = *(uint32_t*)&h0;
            phi1[nb] = *(uint32_t*)&h1;
            __nv_bfloat162 e0 = __float22bfloat162_rn(make_float2(
                p00 - __bfloat162float(h0.x), p01 - __bfloat162float(h0.y)));
            __nv_bfloat162 e1 = __float22bfloat162_rn(make_float2(
                p10 - __bfloat162float(h1.x), p11 - __bfloat162float(h1.y)));
            plo0[nb] = *(uint32_t*)&e0;
            plo1[nb] = *(uint32_t*)&e1;
        }
        ps0 += __shfl_xor_sync(0xffffffffu, ps0, 1);
        ps0 += __shfl_xor_sync(0xffffffffu, ps0, 2);
        ps1 += __shfl_xor_sync(0xffffffffu, ps1, 1);
        ps1 += __shfl_xor_sync(0xffffffffu, ps1, 2);
        l0 = l0 * cr0 + ps0;  m0 = m0n;
        l1 = l1 * cr1 + ps1;  m1 = m1n;
        #pragma unroll
        for (int nb = 0; nb < 8; nb++) {
            O[nb][0] *= cr0; O[nb][1] *= cr0;
            O[nb][2] *= cr1; O[nb][3] *= cr1;
        }

        #pragma unroll
        for (int ks = 0; ks < 4; ks++) {
            uint32_t ahi[4] = { phi0[2*ks], phi1[2*ks], phi0[2*ks+1], phi1[2*ks+1] };
            uint32_t alo[4] = { plo0[2*ks], plo1[2*ks], plo0[2*ks+1], plo1[2*ks+1] };
            #pragma unroll
            for (int nb = 0; nb < 8; nb++) {
                uint32_t bhv[2];
                bhv[0] = sV[(ks*8 + tq    ) * SVS + nb*8 + tg];
                bhv[1] = sV[(ks*8 + tq + 4) * SVS + nb*8 + tg];
                mma_bf16(O[nb], ahi, bhv);
                mma_bf16(O[nb], alo, bhv);
            }
            #pragma unroll
            for (int nb = 0; nb < 8; nb++) {
                uint32_t blv[2];
                blv[0] = sV[(32 + ks*8 + tq    ) * SVS + nb*8 + tg];
                blv[1] = sV[(32 + ks*8 + tq + 4) * SVS + nb*8 + tg];
                mma_bf16(O[nb], ahi, blv);
            }
        }
    }

    const float inv0 = 1.f / l0;
    const float inv1 = 1.f / l1;
    const int b = bh / H_, h = bh % H_;
    #pragma unroll
    for (int nb = 0; nb < 8; nb++) {
        const int d = nb * 8 + 2 * tq;
        *(float2*)(ctx + ((size_t)b * T_ + row0) * C_ + h * 64 + d) =
            make_float2(O[nb][0] * inv0, O[nb][1] * inv0);
        *(float2*)(ctx + ((size_t)b * T_ + row1) * C_ + h * 64 + d) =
            make_float2(O[nb][2] * inv1, O[nb][3] * inv1);
    }
}

// ---------------------------------------------------------------------------
extern "C" void kernel_launch(void* const* d_in, const int* in_sizes, int n_in,
                              void* d_out, int out_size)
{
    (void)in_sizes; (void)n_in; (void)out_size;
    const float* x  = (const float*)d_in[0];
    const float* wq = (const float*)d_in[1];
    const float* wk = (const float*)d_in[2];
    const float* wv = (const float*)d_in[3];
    const float* wo = (const float*)d_in[4];
    float* out = (float*)d_out;

    float *v, *ctx;
    __nv_bfloat16 *x2, *ctx2, *wqkv2, *wo2, *q2, *k2;
    uint32_t *vph, *vpl;
    cudaGetSymbolAddress((void**)&v,     g_v);
    cudaGetSymbolAddress((void**)&ctx,   g_ctx);
    cudaGetSymbolAddress((void**)&x2,    g_x2);
    cudaGetSymbolAddress((void**)&ctx2,  g_ctx2);
    cudaGetSymbolAddress((void**)&wqkv2, g_wqkv2);
    cudaGetSymbolAddress((void**)&wo2,   g_wo2);
    cudaGetSymbolAddress((void**)&q2,    g_q2);
    cudaGetSymbolAddress((void**)&k2,    g_k2);
    cudaGetSymbolAddress((void**)&vph,   g_vph);
    cudaGetSymbolAddress((void**)&vpl,   g_vpl);

    const int nx = BT_ * C_;
    const int nw = C_ * C_;
    conv_hilo<0><<<(nx + 255) / 256, 256>>>(x,  x2,  nx);
    conv_hilo<1><<<(nw + 255) / 256, 256>>>(wq, wqkv2,                      nw);
    conv_hilo<1><<<(nw + 255) / 256, 256>>>(wk, wqkv2 + (size_t)768  * K2, nw);
    conv_hilo<1><<<(nw + 255) / 256, 256>>>(wv, wqkv2 + (size_t)1536 * K2, nw);
    conv_hilo<1><<<(nw + 255) / 256, 256>>>(wo, wo2, nw);

    // merged QKV GEMM: grid 18 x 64
    gemm_bf16<4><<<dim3(N3 / 128, BT_ / 128), 256>>>(x2, wqkv2, q2, k2, v);

    const int nvp = BH_ * (T_/2) * D_;
    conv_vp<<<(nvp + 255) / 256, 256>>>(v, vph, vpl, nvp);

    cudaFuncSetAttribute(attn_mma, cudaFuncAttributeMaxDynamicSharedMemorySize, ATTN_SMEM);
    attn_mma<<<dim3(T_ / 128, BH_), 256, ATTN_SMEM>>>(q2, k2, vph, vpl, ctx);

    conv_hilo<0><<<(nx + 255) / 256, 256>>>(ctx, ctx2, nx);

    // O GEMM: 128x64 tile, grid 12 x 64
    gemm_bf16<1><<<dim3(C_ / 64, BT_ / 128), 256>>>(ctx2, wo2, out, nullptr, nullptr);
}

// round 15
// speedup vs baseline: 4.1780x; 1.0679x over previous
#include <cuda_runtime.h>
#include <cuda_bf16.h>
#include <cstdint>
#include <math.h>

#define B_ 2
#define T_ 4096
#define H_ 12
#define D_ 64
#define C_ 768
#define BT_ (B_*T_)
#define BH_ (B_*H_)
#define K2 2304   // 3 * C_ : [hi | lo | hi] x [hi | hi | lo]
#define D2 192    // 3 * D_ for attention QK split
#define N3 2304   // merged QKV output width (3 * 768)

// Scratch (static device globals — allocation-free per harness rules)
__device__ float g_v[(size_t)BH_*T_*D_];
__device__ float g_ctx[(size_t)BT_*C_];
__device__ __nv_bfloat16 g_x2[(size_t)BT_*K2];
__device__ __nv_bfloat16 g_ctx2[(size_t)BT_*K2];
__device__ __nv_bfloat16 g_wqkv2[(size_t)N3*K2];
__device__ __nv_bfloat16 g_wo2[(size_t)C_*K2];
__device__ __nv_bfloat16 g_q2[(size_t)BH_*T_*D2];
__device__ __nv_bfloat16 g_k2[(size_t)BH_*T_*D2];
__device__ uint32_t g_vph[(size_t)BH_*(T_/2)*D_];
__device__ uint32_t g_vpl[(size_t)BH_*(T_/2)*D_];

// ---------------------------------------------------------------------------
// conversions (unchanged)
// ---------------------------------------------------------------------------
template<int ISW>
__global__ __launch_bounds__(256) void conv_hilo(const float* __restrict__ in,
                                                 __nv_bfloat16* __restrict__ out,
                                                 int nelem)
{
    int idx = blockIdx.x * 256 + threadIdx.x;
    if (idx >= nelem) return;
    int r = idx / C_, c = idx % C_;
    float x = in[idx];
    __nv_bfloat16 hi = __float2bfloat16(x);
    __nv_bfloat16 lo = __float2bfloat16(x - __bfloat162float(hi));
    __nv_bfloat16* o = out + (size_t)r * K2;
    if (ISW) { o[c] = hi; o[c + C_] = hi; o[c + 2*C_] = lo; }
    else     { o[c] = hi; o[c + C_] = lo; o[c + 2*C_] = hi; }
}

__global__ __launch_bounds__(256) void conv_vp(const float* __restrict__ in,
                                               uint32_t* __restrict__ vph,
                                               uint32_t* __restrict__ vpl,
                                               int nelem)
{
    int idx = blockIdx.x * 256 + threadIdx.x;
    if (idx >= nelem) return;
    int d  = idx & 63;
    int t2 = idx >> 6;
    float v0 = in[(size_t)(2*t2) * 64 + d];
    float v1 = in[(size_t)(2*t2) * 64 + 64 + d];
    __nv_bfloat16 h0 = __float2bfloat16(v0);
    __nv_bfloat16 h1 = __float2bfloat16(v1);
    __nv_bfloat16 l0 = __float2bfloat16(v0 - __bfloat162float(h0));
    __nv_bfloat16 l1 = __float2bfloat16(v1 - __bfloat162float(h1));
    __nv_bfloat162 hp = __halves2bfloat162(h0, h1);
    __nv_bfloat162 lp = __halves2bfloat162(l0, l1);
    vph[idx] = *(uint32_t*)&hp;
    vpl[idx] = *(uint32_t*)&lp;
}

// ---------------------------------------------------------------------------
// async + mma helpers
// ---------------------------------------------------------------------------
__device__ __forceinline__ void cp16(void* dst, const void* src)
{
    uint32_t d = (uint32_t)__cvta_generic_to_shared(dst);
    asm volatile("cp.async.cg.shared.global [%0], [%1], 16;\n" :: "r"(d), "l"(src));
}
__device__ __forceinline__ void cp_commit()  { asm volatile("cp.async.commit_group;\n" ::: "memory"); }
__device__ __forceinline__ void cp_wait2()   { asm volatile("cp.async.wait_group 2;\n" ::: "memory"); }
__device__ __forceinline__ void cp_wait1()   { asm volatile("cp.async.wait_group 1;\n" ::: "memory"); }
__device__ __forceinline__ void cp_wait0()   { asm volatile("cp.async.wait_group 0;\n" ::: "memory"); }

__device__ __forceinline__ void mma_bf16(float c[4], const uint32_t a[4], const uint32_t b[2])
{
    asm volatile(
        "mma.sync.aligned.m16n8k16.row.col.f32.bf16.bf16.f32 "
        "{%0,%1,%2,%3}, {%4,%5,%6,%7}, {%8,%9}, {%0,%1,%2,%3};"
        : "+f"(c[0]), "+f"(c[1]), "+f"(c[2]), "+f"(c[3])
        : "r"(a[0]), "r"(a[1]), "r"(a[2]), "r"(a[3]), "r"(b[0]), "r"(b[1]));
}
__device__ __forceinline__ void ldsm4(uint32_t& r0, uint32_t& r1, uint32_t& r2, uint32_t& r3,
                                      uint32_t addr)
{
    asm volatile("ldmatrix.sync.aligned.m8n8.x4.shared.b16 {%0,%1,%2,%3}, [%4];"
                 : "=r"(r0), "=r"(r1), "=r"(r2), "=r"(r3) : "r"(addr));
}

// ---------------------------------------------------------------------------
// HMMA merged QKV GEMM, 3-stage cp.async + ldmatrix fragment loads.
// (8192 x 2304) = x2 @ wqkv2^T, CTA 128x128, 8 warps 4(m)x2(n).
// Epilogue: sec 0 Q-split [hi|lo|hi], sec 1 K-split [hi|hi|lo], sec 2 V fp32.
// ---------------------------------------------------------------------------
#define SAS 40
#define NKC (K2/32)              // 72
#define STG_H (128*SAS)          // 5120 halves per matrix per stage
#define STAGE_H (2*STG_H)        // A+B per stage
#define QKV_SMEM (3*STAGE_H*2)   // 61440 bytes

__global__ __launch_bounds__(256, 2) void gemm_qkv(
    const __nv_bfloat16* __restrict__ A, const __nv_bfloat16* __restrict__ W,
    __nv_bfloat16* __restrict__ q2o, __nv_bfloat16* __restrict__ k2o,
    float* __restrict__ vo)
{
    extern __shared__ __nv_bfloat16 dsm[];
    const uint32_t smem0 = (uint32_t)__cvta_generic_to_shared(dsm);

    const int tid  = threadIdx.x;
    const int wid  = tid >> 5, lane = tid & 31;
    const int m0   = blockIdx.y * 128, n0 = blockIdx.x * 128;
    const int wm   = (wid & 3) * 32;
    const int wn   = (wid >> 2) * 64;
    const int tq   = lane & 3;
    const int tg   = lane >> 2;

    const int lr  = tid >> 2;          // 0..63
    const int lc8 = (tid & 3) << 3;    // 0,8,16,24

    // ldmatrix lane-address components
    const int a_row_off = (lane & 7) + ((lane >> 3) & 1) * 8;   // within 16-row A tile
    const int a_col_off = ((lane >> 4) & 1) * 8;                // 0 or 8 halves
    const int b_sub     = ((lane >> 4) & 1);                    // B pair member
    const int b_row_off = (lane & 7);
    const int b_col_off = ((lane >> 3) & 1) * 8;

    float c[2][8][4];
    #pragma unroll
    for (int mb = 0; mb < 2; mb++)
        #pragma unroll
        for (int nb = 0; nb < 8; nb++)
            #pragma unroll
            for (int i = 0; i < 4; i++) c[mb][nb][i] = 0.f;

    auto issue = [&](int kc, int s) {
        __nv_bfloat16* sA = dsm + s * STAGE_H;
        __nv_bfloat16* sB = sA + STG_H;
        #pragma unroll
        for (int half = 0; half < 2; half++) {
            int r = lr + half * 64;
            cp16(&sA[r * SAS + lc8], A + (size_t)(m0 + r) * K2 + kc * 32 + lc8);
            cp16(&sB[r * SAS + lc8], W + (size_t)(n0 + r) * K2 + kc * 32 + lc8);
        }
    };

    issue(0, 0); cp_commit();
    issue(1, 1); cp_commit();

    for (int kc = 0; kc < NKC; kc++) {
        const int s = kc % 3;
        if (kc + 2 < NKC) { issue(kc + 2, (kc + 2) % 3); cp_commit(); cp_wait2(); }
        else if (kc + 1 < NKC) cp_wait1();
        else                   cp_wait0();
        __syncthreads();

        const uint32_t aBase = smem0 + (s * STAGE_H) * 2;
        const uint32_t bBase = aBase + STG_H * 2;

        #pragma unroll
        for (int ks = 0; ks < 32; ks += 16) {
            uint32_t af[2][4], bf[8][2];
            #pragma unroll
            for (int mb = 0; mb < 2; mb++) {
                const uint32_t addr = aBase +
                    ((wm + mb * 16 + a_row_off) * SAS + ks + a_col_off) * 2;
                ldsm4(af[mb][0], af[mb][1], af[mb][2], af[mb][3], addr);
            }
            #pragma unroll
            for (int np = 0; np < 4; np++) {
                const uint32_t addr = bBase +
                    ((wn + (np * 2 + b_sub) * 8 + b_row_off) * SAS + ks + b_col_off) * 2;
                ldsm4(bf[2*np][0], bf[2*np][1], bf[2*np+1][0], bf[2*np+1][1], addr);
            }
            #pragma unroll
            for (int mb = 0; mb < 2; mb++)
                #pragma unroll
                for (int nb = 0; nb < 8; nb++)
                    mma_bf16(c[mb][nb], af[mb], bf[nb]);
        }
        __syncthreads();
    }

    // ---- epilogue (same as R12 merged mode) ----
    #pragma unroll
    for (int mb = 0; mb < 2; mb++) {
        #pragma unroll
        for (int nb = 0; nb < 8; nb++) {
            const int m = m0 + wm + mb * 16 + tg;
            const int n = n0 + wn + nb * 8 + tq * 2;
            const int sec  = n / 768;
            const int nloc = n - sec * 768;
            const int b = m >> 12, t = m & 4095;
            const int h = nloc >> 6, d = nloc & 63;
            if (sec == 2) {
                float* p = vo + (((size_t)(b * H_ + h)) * T_ + t) * D_ + d;
                *(float2*)p            = make_float2(c[mb][nb][0], c[mb][nb][1]);
                *(float2*)(p + 8 * D_) = make_float2(c[mb][nb][2], c[mb][nb][3]);
            } else {
                __nv_bfloat16* out = (sec == 0) ? q2o : k2o;
                #pragma unroll
                for (int half = 0; half < 2; half++) {
                    const float v0 = c[mb][nb][2*half + 0];
                    const float v1 = c[mb][nb][2*half + 1];
                    __nv_bfloat16 h0 = __float2bfloat16(v0);
                    __nv_bfloat16 h1 = __float2bfloat16(v1);
                    __nv_bfloat16 e0 = __float2bfloat16(v0 - __bfloat162float(h0));
                    __nv_bfloat16 e1 = __float2bfloat16(v1 - __bfloat162float(h1));
                    __nv_bfloat162 hp = __halves2bfloat162(h0, h1);
                    __nv_bfloat162 ep = __halves2bfloat162(e0, e1);
                    __nv_bfloat16* p = out + ((size_t)(b * H_ + h) * T_ + t + half * 8) * D2 + d;
                    if (sec == 0) {   // Q: [hi | lo | hi]
                        *(__nv_bfloat162*)(p)       = hp;
                        *(__nv_bfloat162*)(p + 64)  = ep;
                        *(__nv_bfloat162*)(p + 128) = hp;
                    } else {          // K: [hi | hi | lo]
                        *(__nv_bfloat162*)(p)       = hp;
                        *(__nv_bfloat162*)(p + 64)  = hp;
                        *(__nv_bfloat162*)(p + 128) = ep;
                    }
                }
            }
        }
    }
}

// ---------------------------------------------------------------------------
// HMMA O-projection GEMM, 2-stage cp.async + ldmatrix. NT=64 tile.
// ---------------------------------------------------------------------------
__global__ __launch_bounds__(256, 2) void gemm_o(const __nv_bfloat16* __restrict__ A,
                                                 const __nv_bfloat16* __restrict__ Bm,
                                                 float* __restrict__ out)
{
    constexpr int NT = 64;
    constexpr int NB = 4;

    __shared__ __align__(16) __nv_bfloat16 sA[2][128][SAS];
    __shared__ __align__(16) __nv_bfloat16 sB[2][NT][SAS];

    const int tid  = threadIdx.x;
    const int wid  = tid >> 5, lane = tid & 31;
    const int m0   = blockIdx.y * 128, n0 = blockIdx.x * NT;
    const int wm   = (wid & 3) * 32;
    const int wn   = (wid >> 2) * (NT / 2);
    const int tq   = lane & 3;
    const int tg   = lane >> 2;

    const int lr  = tid >> 2;
    const int lc8 = (tid & 3) << 3;

    const int a_row_off = (lane & 7) + ((lane >> 3) & 1) * 8;
    const int a_col_off = ((lane >> 4) & 1) * 8;
    const int b_sub     = ((lane >> 4) & 1);
    const int b_row_off = (lane & 7);
    const int b_col_off = ((lane >> 3) & 1) * 8;

    const uint32_t sA0 = (uint32_t)__cvta_generic_to_shared(&sA[0][0][0]);
    const uint32_t sB0 = (uint32_t)__cvta_generic_to_shared(&sB[0][0][0]);

    float c[2][NB][4];
    #pragma unroll
    for (int mb = 0; mb < 2; mb++)
        #pragma unroll
        for (int nb = 0; nb < NB; nb++)
            #pragma unroll
            for (int i = 0; i < 4; i++) c[mb][nb][i] = 0.f;

    auto issue = [&](int kc, int s) {
        #pragma unroll
        for (int half = 0; half < 2; half++) {
            int r = lr + half * 64;
            cp16(&sA[s][r][lc8], A + (size_t)(m0 + r) * K2 + kc * 32 + lc8);
        }
        cp16(&sB[s][lr][lc8], Bm + (size_t)(n0 + lr) * K2 + kc * 32 + lc8);
    };

    issue(0, 0);
    cp_commit();

    for (int kc = 0; kc < NKC; kc++) {
        const int s = kc & 1;
        if (kc + 1 < NKC) { issue(kc + 1, s ^ 1); cp_commit(); cp_wait1(); }
        else              { cp_wait0(); }
        __syncthreads();

        const uint32_t aBase = sA0 + s * (128 * SAS * 2);
        const uint32_t bBase = sB0 + s * (NT * SAS * 2);

        #pragma unroll
        for (int ks = 0; ks < 32; ks += 16) {
            uint32_t af[2][4], bf[NB][2];
            #pragma unroll
            for (int mb = 0; mb < 2; mb++) {
                const uint32_t addr = aBase +
                    ((wm + mb * 16 + a_row_off) * SAS + ks + a_col_off) * 2;
                ldsm4(af[mb][0], af[mb][1], af[mb][2], af[mb][3], addr);
            }
            #pragma unroll
            for (int np = 0; np < 2; np++) {
                const uint32_t addr = bBase +
                    ((wn + (np * 2 + b_sub) * 8 + b_row_off) * SAS + ks + b_col_off) * 2;
                ldsm4(bf[2*np][0], bf[2*np][1], bf[2*np+1][0], bf[2*np+1][1], addr);
            }
            #pragma unroll
            for (int mb = 0; mb < 2; mb++)
                #pragma unroll
                for (int nb = 0; nb < NB; nb++)
                    mma_bf16(c[mb][nb], af[mb], bf[nb]);
        }
        __syncthreads();
    }

    #pragma unroll
    for (int mb = 0; mb < 2; mb++) {
        #pragma unroll
        for (int nb = 0; nb < NB; nb++) {
            const int m = m0 + wm + mb * 16 + tg;
            const int n = n0 + wn + nb * 8 + tq * 2;
            float* p = out + (size_t)m * C_ + n;
            *(float2*)p            = make_float2(c[mb][nb][0], c[mb][nb][1]);
            *(float2*)(p + 8 * C_) = make_float2(c[mb][nb][2], c[mb][nb][3]);
        }
    }
}

// ---------------------------------------------------------------------------
// HMMA causal flash attention (unchanged from R8/R12).
// ---------------------------------------------------------------------------
#define SQS 100
#define SVS 72
#define ATTN_SMEM ((128*SQS + 64*SQS + 64*SVS) * 4)   // 95232 B

__global__ __launch_bounds__(256, 1) void attn_mma(const __nv_bfloat16* __restrict__ Q2,
                                                   const __nv_bfloat16* __restrict__ Ksp,
                                                   const uint32_t* __restrict__ Vph,
                                                   const uint32_t* __restrict__ Vpl,
                                                   float* __restrict__ ctx)
{
    extern __shared__ uint32_t smem_u[];
    uint32_t* sQ = smem_u;
    uint32_t* sK = smem_u + 128 * SQS;
    uint32_t* sV = smem_u + 128 * SQS + 64 * SQS;

    const int tid = threadIdx.x;
    const int w   = tid >> 5;
    const int lane = tid & 31;
    const int tg  = lane >> 2;
    const int tq  = lane & 3;
    const int qt  = blockIdx.x;
    const int bh  = blockIdx.y;
    const int qb  = qt * 128;
    const int rbase = qb + w * 16;
    const int row0 = rbase + tg;
    const int row1 = row0 + 8;

    {
        const __nv_bfloat16* qsrc = Q2 + ((size_t)bh * T_ + qb) * D2;
        int r = tid >> 1;
        #pragma unroll
        for (int i = 0; i < 12; i++) {
            int c4 = (tid & 1) + 2 * i;
            *(uint4*)(sQ + r * SQS + c4 * 4) = *(const uint4*)(qsrc + (size_t)r * D2 + c4 * 8);
        }
    }

    float O[8][4];
    #pragma unroll
    for (int nb = 0; nb < 8; nb++)
        #pragma unroll
        for (int i = 0; i < 4; i++) O[nb][i] = 0.f;
    float m0 = -1e30f, m1 = -1e30f, l0 = 0.f, l1 = 0.f;

    const int nkt = 2 * qt + 2;
    for (int kt = 0; kt < nkt; kt++) {
        const int ktbase = kt * 64;
        __syncthreads();
        {
            int r  = tid >> 2;
            int cb = tid & 3;
            const __nv_bfloat16* ksrc = Ksp + ((size_t)bh * T_ + ktbase + r) * D2;
            #pragma unroll
            for (int i = 0; i < 6; i++) {
                int c4 = cb + 4 * i;
                *(uint4*)(sK + r * SQS + c4 * 4) = *(const uint4*)(ksrc + c4 * 8);
            }
            const uint32_t* vsrc = (r < 32)
                ? Vph + ((size_t)bh * (T_/2) + ktbase/2 + r) * 64
                : Vpl + ((size_t)bh * (T_/2) + ktbase/2 + (r - 32)) * 64;
            #pragma unroll
            for (int i = 0; i < 4; i++) {
                int c4 = cb + 4 * i;
                *(uint4*)(sV + r * SVS + c4 * 4) = *(const uint4*)(vsrc + c4 * 4);
            }
        }
        __syncthreads();

        if (ktbase > rbase + 15) continue;

        float S[8][4];
        #pragma unroll
        for (int nb = 0; nb < 8; nb++)
            #pragma unroll
            for (int i = 0; i < 4; i++) S[nb][i] = 0.f;

        #pragma unroll
        for (int ks = 0; ks < 12; ks++) {
            uint32_t a[4];
            a[0] = sQ[(w*16 + tg    ) * SQS + ks*8 + tq    ];
            a[1] = sQ[(w*16 + tg + 8) * SQS + ks*8 + tq    ];
            a[2] = sQ[(w*16 + tg    ) * SQS + ks*8 + tq + 4];
            a[3] = sQ[(w*16 + tg + 8) * SQS + ks*8 + tq + 4];
            #pragma unroll
            for (int nb = 0; nb < 8; nb++) {
                uint32_t b[2];
                b[0] = sK[(nb*8 + tg) * SQS + ks*8 + tq    ];
                b[1] = sK[(nb*8 + tg) * SQS + ks*8 + tq + 4];
                mma_bf16(S[nb], a, b);
            }
        }

        #pragma unroll
        for (int nb = 0; nb < 8; nb++)
            #pragma unroll
            for (int i = 0; i < 4; i++) S[nb][i] *= 0.125f;

        if (ktbase + 63 > rbase) {
            #pragma unroll
            for (int nb = 0; nb < 8; nb++) {
                int col0 = ktbase + nb*8 + 2*tq;
                int col1 = col0 + 1;
                if (col0 > row0) S[nb][0] = -1e30f;
                if (col1 > row0) S[nb][1] = -1e30f;
                if (col0 > row1) S[nb][2] = -1e30f;
                if (col1 > row1) S[nb][3] = -1e30f;
            }
        }

        float mx0 = -1e30f, mx1 = -1e30f;
        #pragma unroll
        for (int nb = 0; nb < 8; nb++) {
            mx0 = fmaxf(mx0, fmaxf(S[nb][0], S[nb][1]));
            mx1 = fmaxf(mx1, fmaxf(S[nb][2], S[nb][3]));
        }
        mx0 = fmaxf(mx0, __shfl_xor_sync(0xffffffffu, mx0, 1));
        mx0 = fmaxf(mx0, __shfl_xor_sync(0xffffffffu, mx0, 2));
        mx1 = fmaxf(mx1, __shfl_xor_sync(0xffffffffu, mx1, 1));
        mx1 = fmaxf(mx1, __shfl_xor_sync(0xffffffffu, mx1, 2));

        const float m0n = fmaxf(m0, mx0);
        const float m1n = fmaxf(m1, mx1);
        const float cr0 = __expf(m0 - m0n);
        const float cr1 = __expf(m1 - m1n);

        uint32_t phi0[8], phi1[8], plo0[8], plo1[8];
        float ps0 = 0.f, ps1 = 0.f;
        #pragma unroll
        for (int nb = 0; nb < 8; nb++) {
            float p00 = __expf(S[nb][0] - m0n);
            float p01 = __expf(S[nb][1] - m0n);
            float p10 = __expf(S[nb][2] - m1n);
            float p11 = __expf(S[nb][3] - m1n);
            ps0 += p00 + p01;
            ps1 += p10 + p11;
            __nv_bfloat162 h0 = __float22bfloat162_rn(make_float2(p00, p01));
            __nv_bfloat162 h1 = __float22bfloat162_rn(make_float2(p10, p11));
            phi0[nb] = *(uint32_t*)&h0;
            phi1[nb] = *(uint32_t*)&h1;
            __nv_bfloat162 e0 = __float22bfloat162_rn(make_float2(
                p00 - __bfloat162float(h0.x), p01 - __bfloat162float(h0.y)));
            __nv_bfloat162 e1 = __float22bfloat162_rn(make_float2(
                p10 - __bfloat162float(h1.x), p11 - __bfloat162float(h1.y)));
            plo0[nb] = *(uint32_t*)&e0;
            plo1[nb] = *(uint32_t*)&e1;
        }
        ps0 += __shfl_xor_sync(0xffffffffu, ps0, 1);
        ps0 += __shfl_xor_sync(0xffffffffu, ps0, 2);
        ps1 += __shfl_xor_sync(0xffffffffu, ps1, 1);
        ps1 += __shfl_xor_sync(0xffffffffu, ps1, 2);
        l0 = l0 * cr0 + ps0;  m0 = m0n;
        l1 = l1 * cr1 + ps1;  m1 = m1n;
        #pragma unroll
        for (int nb = 0; nb < 8; nb++) {
            O[nb][0] *= cr0; O[nb][1] *= cr0;
            O[nb][2] *= cr1; O[nb][3] *= cr1;
        }

        #pragma unroll
        for (int ks = 0; ks < 4; ks++) {
            uint32_t ahi[4] = { phi0[2*ks], phi1[2*ks], phi0[2*ks+1], phi1[2*ks+1] };
            uint32_t alo[4] = { plo0[2*ks], plo1[2*ks], plo0[2*ks+1], plo1[2*ks+1] };
            #pragma unroll
            for (int nb = 0; nb < 8; nb++) {
                uint32_t bhv[2];
                bhv[0] = sV[(ks*8 + tq    ) * SVS + nb*8 + tg];
                bhv[1] = sV[(ks*8 + tq + 4) * SVS + nb*8 + tg];
                mma_bf16(O[nb], ahi, bhv);
                mma_bf16(O[nb], alo, bhv);
            }
            #pragma unroll
            for (int nb = 0; nb < 8; nb++) {
                uint32_t blv[2];
                blv[0] = sV[(32 + ks*8 + tq    ) * SVS + nb*8 + tg];
                blv[1] = sV[(32 + ks*8 + tq + 4) * SVS + nb*8 + tg];
                mma_bf16(O[nb], ahi, blv);
            }
        }
    }

    const float inv0 = 1.f / l0;
    const float inv1 = 1.f / l1;
    const int b = bh / H_, h = bh % H_;
    #pragma unroll
    for (int nb = 0; nb < 8; nb++) {
        const int d = nb * 8 + 2 * tq;
        *(float2*)(ctx + ((size_t)b * T_ + row0) * C_ + h * 64 + d) =
            make_float2(O[nb][0] * inv0, O[nb][1] * inv0);
        *(float2*)(ctx + ((size_t)b * T_ + row1) * C_ + h * 64 + d) =
            make_float2(O[nb][2] * inv1, O[nb][3] * inv1);
    }
}

// ---------------------------------------------------------------------------
extern "C" void kernel_launch(void* const* d_in, const int* in_sizes, int n_in,
                              void* d_out, int out_size)
{
    (void)in_sizes; (void)n_in; (void)out_size;
    const float* x  = (const float*)d_in[0];
    const float* wq = (const float*)d_in[1];
    const float* wk = (const float*)d_in[2];
    const float* wv = (const float*)d_in[3];
    const float* wo = (const float*)d_in[4];
    float* out = (float*)d_out;

    float *v, *ctx;
    __nv_bfloat16 *x2, *ctx2, *wqkv2, *wo2, *q2, *k2;
    uint32_t *vph, *vpl;
    cudaGetSymbolAddress((void**)&v,     g_v);
    cudaGetSymbolAddress((void**)&ctx,   g_ctx);
    cudaGetSymbolAddress((void**)&x2,    g_x2);
    cudaGetSymbolAddress((void**)&ctx2,  g_ctx2);
    cudaGetSymbolAddress((void**)&wqkv2, g_wqkv2);
    cudaGetSymbolAddress((void**)&wo2,   g_wo2);
    cudaGetSymbolAddress((void**)&q2,    g_q2);
    cudaGetSymbolAddress((void**)&k2,    g_k2);
    cudaGetSymbolAddress((void**)&vph,   g_vph);
    cudaGetSymbolAddress((void**)&vpl,   g_vpl);

    const int nx = BT_ * C_;
    const int nw = C_ * C_;
    conv_hilo<0><<<(nx + 255) / 256, 256>>>(x,  x2,  nx);
    conv_hilo<1><<<(nw + 255) / 256, 256>>>(wq, wqkv2,                      nw);
    conv_hilo<1><<<(nw + 255) / 256, 256>>>(wk, wqkv2 + (size_t)768  * K2, nw);
    conv_hilo<1><<<(nw + 255) / 256, 256>>>(wv, wqkv2 + (size_t)1536 * K2, nw);
    conv_hilo<1><<<(nw + 255) / 256, 256>>>(wo, wo2, nw);

    // merged QKV GEMM: grid 18 x 64, 3-stage pipeline, dynamic smem
    cudaFuncSetAttribute(gemm_qkv, cudaFuncAttributeMaxDynamicSharedMemorySize, QKV_SMEM);
    gemm_qkv<<<dim3(N3 / 128, BT_ / 128), 256, QKV_SMEM>>>(x2, wqkv2, q2, k2, v);

    const int nvp = BH_ * (T_/2) * D_;
    conv_vp<<<(nvp + 255) / 256, 256>>>(v, vph, vpl, nvp);

    cudaFuncSetAttribute(attn_mma, cudaFuncAttributeMaxDynamicSharedMemorySize, ATTN_SMEM);
    attn_mma<<<dim3(T_ / 128, BH_), 256, ATTN_SMEM>>>(q2, k2, vph, vpl, ctx);

    conv_hilo<0><<<(nx + 255) / 256, 256>>>(ctx, ctx2, nx);

    // O GEMM: HMMA 128x64 tile, grid 12 x 64
    gemm_o<<<dim3(C_ / 64, BT_ / 128), 256>>>(ctx2, wo2, out);
}